// round 2
// baseline (speedup 1.0000x reference)
#include <cuda_runtime.h>
#include <math.h>

#define BATCH 1024
#define NFEAT 65536
#define ZD 32
#define NG 16
#define NF 64
#define NR 32
#define KC 64
#define KLEN 1024

__device__ float g_zpart[KC * BATCH * 64];
__device__ float g_s2part[KC * BATCH];
__device__ float g_zraw[BATCH * 64];
__device__ float g_s2[BATCH];
__device__ float g_spF[NG * ZD * NF];
__device__ float g_spR1[NG * ZD * NR];
__device__ float g_spR2[NG * ZD * NR];
__device__ float g_GG[NG * ZD * ZD];
__device__ float g_w[BATCH * ZD];
__device__ float g_zs2[BATCH * ZD];
__device__ float g_kld[BATCH];
__device__ float g_PF[BATCH * ZD];
__device__ float g_perb[BATCH];
__device__ float g_varloss;

static __device__ __forceinline__ float softplusf(float x) {
    return fmaxf(x, 0.f) + log1pf(expf(-fabsf(x)));
}

// softplus of the three factor tensors
__global__ void k_sp(const float* __restrict__ ff, const float* __restrict__ r1,
                     const float* __restrict__ r2) {
    int i = blockIdx.x * 256 + threadIdx.x;
    const int nF = NG * ZD * NF, nR = NG * ZD * NR;
    if (i < nF) g_spF[i] = softplusf(ff[i]);
    else if (i < nF + nR) g_spR1[i - nF] = softplusf(r1[i - nF]);
    else if (i < nF + 2 * nR) g_spR2[i - nF - nR] = softplusf(r2[i - nF - nR]);
}

// per-group Gram products GG = Gf .* G1 .* G2   [16][32][32]
__global__ void k_gram() {
    __shared__ float s1[ZD * NR], s2m[ZD * NR], sf[ZD * NF];
    int g = blockIdx.x, t = threadIdx.x;
    for (int i = t; i < ZD * NR; i += 256) {
        s1[i] = g_spR1[g * ZD * NR + i];
        s2m[i] = g_spR2[g * ZD * NR + i];
    }
    for (int i = t; i < ZD * NF; i += 256) sf[i] = g_spF[g * ZD * NF + i];
    __syncthreads();
    for (int q = t; q < ZD * ZD; q += 256) {
        int z = q >> 5, z2 = q & 31;
        float a = 0.f, b = 0.f, c = 0.f;
        #pragma unroll
        for (int r = 0; r < NR; r++) {
            a += s1[z * NR + r] * s1[z2 * NR + r];
            b += s2m[z * NR + r] * s2m[z2 * NR + r];
        }
        #pragma unroll
        for (int f = 0; f < NF; f++) c += sf[z * NF + f] * sf[z2 * NF + f];
        g_GG[g * ZD * ZD + q] = a * b * c;
    }
}

// freq_loss + roi_loss (ddof=1 variance over groups)
__global__ void k_varloss() {
    __shared__ float rf[256], rr[256];
    int t = threadIdx.x;
    float af = 0.f, ar = 0.f;
    for (int idx = t; idx < 4096; idx += 256) {
        float s = 0.f, ss = 0.f;
        if (idx < 2048) {
            #pragma unroll
            for (int g = 0; g < 16; g++) { float x = g_spF[g * 2048 + idx]; s += x; ss += x * x; }
            af += (ss - s * s * (1.f / 16.f)) * (1.f / 15.f);
        } else if (idx < 3072) {
            int j = idx - 2048;
            #pragma unroll
            for (int g = 0; g < 16; g++) { float x = g_spR1[g * 1024 + j]; s += x; ss += x * x; }
            ar += (ss - s * s * (1.f / 16.f)) * (1.f / 15.f);
        } else {
            int j = idx - 3072;
            #pragma unroll
            for (int g = 0; g < 16; g++) { float x = g_spR2[g * 1024 + j]; s += x; ss += x * x; }
            ar += (ss - s * s * (1.f / 16.f)) * (1.f / 15.f);
        }
    }
    rf[t] = af; rr[t] = ar;
    __syncthreads();
    for (int o = 128; o > 0; o >>= 1) {
        if (t < o) { rf[t] += rf[t + o]; rr[t] += rr[t + o]; }
        __syncthreads();
    }
    if (t == 0) g_varloss = rf[0] * (1.f / 64.f) + rr[0] * (1.f / 32.f);
}

// big GEMM: zpart[kc][b][0:32]=flat@W1 chunk, [32:64]=flat@W2 chunk; plus s2 partials
// grid (64 kchunks, 8 btiles), 128 threads, BM=128 BN=64 BK=16, 8x8 register tiles
__global__ void __launch_bounds__(128) k_gemm(const float* __restrict__ feat,
                                              const float* __restrict__ W1,
                                              const float* __restrict__ W2) {
    __shared__ float As[16][129];
    __shared__ float Bs[16][68];
    __shared__ float s2s[128][4];
    int t = threadIdx.x;
    int kc = blockIdx.x, bt = blockIdx.y;
    const float* fb = feat + (size_t)bt * 128 * NFEAT + (size_t)kc * KLEN;
    int lr = t >> 2, lk4 = (t & 3) * 4;
    int rbase = t & 15, cbase = (t >> 4) * 8;
    float acc[8][8];
    #pragma unroll
    for (int i = 0; i < 8; i++)
        #pragma unroll
        for (int j = 0; j < 8; j++) acc[i][j] = 0.f;
    float sq[4] = {0.f, 0.f, 0.f, 0.f};

    for (int kt = 0; kt < 64; kt++) {
        #pragma unroll
        for (int i = 0; i < 4; i++) {
            float4 v = *(const float4*)(fb + (size_t)(lr + 32 * i) * NFEAT + kt * 16 + lk4);
            As[lk4 + 0][lr + 32 * i] = v.x;
            As[lk4 + 1][lr + 32 * i] = v.y;
            As[lk4 + 2][lr + 32 * i] = v.z;
            As[lk4 + 3][lr + 32 * i] = v.w;
            sq[i] += v.x * v.x + v.y * v.y + v.z * v.z + v.w * v.w;
        }
        #pragma unroll
        for (int i = 0; i < 2; i++) {
            int q = t * 2 + i;
            int k = q >> 4, c4 = q & 15;
            const float* src = (c4 < 8)
                ? (W1 + ((size_t)kc * KLEN + kt * 16 + k) * 32 + c4 * 4)
                : (W2 + ((size_t)kc * KLEN + kt * 16 + k) * 32 + (c4 - 8) * 4);
            *(float4*)&Bs[k][c4 * 4] = *(const float4*)src;
        }
        __syncthreads();
        #pragma unroll
        for (int k = 0; k < 16; k++) {
            float a[8], b[8];
            #pragma unroll
            for (int i = 0; i < 8; i++) a[i] = As[k][rbase + 16 * i];
            #pragma unroll
            for (int j = 0; j < 8; j++) b[j] = Bs[k][cbase + j];
            #pragma unroll
            for (int i = 0; i < 8; i++)
                #pragma unroll
                for (int j = 0; j < 8; j++) acc[i][j] += a[i] * b[j];
        }
        __syncthreads();
    }
    float* zp = g_zpart + ((size_t)kc * BATCH + bt * 128) * 64;
    #pragma unroll
    for (int i = 0; i < 8; i++)
        #pragma unroll
        for (int j = 0; j < 8; j++)
            zp[(rbase + 16 * i) * 64 + cbase + j] = acc[i][j];
    #pragma unroll
    for (int i = 0; i < 4; i++) s2s[lr + 32 * i][t & 3] = sq[i];
    __syncthreads();
    g_s2part[kc * BATCH + bt * 128 + t] = s2s[t][0] + s2s[t][1] + s2s[t][2] + s2s[t][3];
}

// reduce split-K partials
__global__ void k_reduce() {
    int i = blockIdx.x * 256 + threadIdx.x;
    if (i < BATCH * 64) {
        float s = 0.f;
        for (int kc = 0; kc < KC; kc++) s += g_zpart[(size_t)kc * BATCH * 64 + i];
        g_zraw[i] = s;
    } else if (i < BATCH * 64 + BATCH) {
        int b = i - BATCH * 64;
        float s = 0.f;
        for (int kc = 0; kc < KC; kc++) s += g_s2part[kc * BATCH + b];
        g_s2[b] = s;
    }
}

// VAE head: mu/sigma/kld, reparam, linear layer, softplus weights
__global__ void k_vae(const float* __restrict__ W1, const float* __restrict__ W2,
                      const float* __restrict__ b1, const float* __restrict__ b2,
                      const float* __restrict__ ge, const int* __restrict__ groups,
                      const float* __restrict__ noise, const float* __restrict__ linW,
                      const float* __restrict__ linb) {
    int t = threadIdx.x, b = blockIdx.x * 8 + (t >> 5), z = t & 31;
    int g = groups[b];
    float e0 = ge[g * 2], e1 = ge[g * 2 + 1];
    float mu = g_zraw[b * 64 + z] + b1[z] + e0 * W1[65536 * 32 + z] + e1 * W1[65537 * 32 + z];
    float ls = g_zraw[b * 64 + 32 + z] + b2[z] + e0 * W2[65536 * 32 + z] + e1 * W2[65537 * 32 + z];
    float sig = 1e-6f + expf(ls);
    float kt = -logf(sig) + 0.5f * (sig * sig + mu * mu - 1.f);
    #pragma unroll
    for (int o = 16; o > 0; o >>= 1) kt += __shfl_xor_sync(0xffffffffu, kt, o);
    if (z == 0) g_kld[b] = kt;
    float zs = mu + sig * noise[b * 32 + z];
    float acc = linb[z];
    #pragma unroll
    for (int k = 0; k < 32; k++)
        acc += __shfl_sync(0xffffffffu, zs, k) * linW[k * 32 + z];
    g_zs2[b * 32 + z] = acc;
    g_w[b * 32 + z] = softplusf(acc);
}

// PF[b,z] = sum_f F[z,f] * (R1_z^T * flat[b,f] * R2_z)   (w-independent dot core)
// 1 CTA per b, 256 thr = 16 units x 16 thr, each unit does one f per iter (4 iters)
extern __shared__ float sm[];
__global__ void __launch_bounds__(256) k_P(const float* __restrict__ feat,
                                           const int* __restrict__ groups) {
    float* Ms = sm;                      // 16 tiles, stride 1064 (=32*33 + 8 pad)
    float* R1 = sm + 17024;              // [32][33]
    float* R2 = R1 + 1056;               // [32][33]
    float* Fp = R2 + 1056;               // [32][64]
    int t = threadIdx.x, b = blockIdx.x;
    int g = groups[b];
    for (int i = t; i < ZD * NR; i += 256) {
        int z = i >> 5, r = i & 31;
        R1[z * 33 + r] = g_spR1[g * 1024 + i];
        R2[z * 33 + r] = g_spR2[g * 1024 + i];
    }
    for (int i = t; i < ZD * NF; i += 256) Fp[i] = g_spF[g * 2048 + i];
    int u = t >> 4, v = t & 15;
    int r0 = (v & 3) * 8, z0 = (v >> 2) * 8;
    float accA[8];
    #pragma unroll
    for (int j = 0; j < 8; j++) accA[j] = 0.f;
    const float4* fb = (const float4*)(feat + (size_t)b * NFEAT);
    int mr = (t >> 3) * 33 + (t & 7) * 4;

    for (int it = 0; it < 4; it++) {
        __syncthreads();
        #pragma unroll
        for (int j = 0; j < 16; j++) {
            float4 vv = fb[(it * 16 + j) * 256 + t];
            float* Mj = Ms + j * 1064 + mr;
            Mj[0] = vv.x; Mj[1] = vv.y; Mj[2] = vv.z; Mj[3] = vv.w;
        }
        __syncthreads();
        const float* M = Ms + u * 1064;
        float T[8][8];
        #pragma unroll
        for (int i = 0; i < 8; i++)
            #pragma unroll
            for (int j = 0; j < 8; j++) T[i][j] = 0.f;
        #pragma unroll 4
        for (int s = 0; s < 32; s++) {
            float a[8], bb[8];
            #pragma unroll
            for (int i = 0; i < 8; i++) a[i] = M[(r0 + i) * 33 + s];
            #pragma unroll
            for (int j = 0; j < 8; j++) bb[j] = R2[(z0 + j) * 33 + s];
            #pragma unroll
            for (int i = 0; i < 8; i++)
                #pragma unroll
                for (int j = 0; j < 8; j++) T[i][j] += a[i] * bb[j];
        }
        int f = it * 16 + u;
        #pragma unroll
        for (int j = 0; j < 8; j++) {
            float p = 0.f;
            #pragma unroll
            for (int i = 0; i < 8; i++) p += R1[(z0 + j) * 33 + r0 + i] * T[i][j];
            accA[j] += Fp[(z0 + j) * 64 + f] * p;
        }
    }
    __syncthreads();
    float* red = sm;  // [256][8]
    #pragma unroll
    for (int j = 0; j < 8; j++) red[t * 8 + j] = accA[j];
    __syncthreads();
    if (t < 32) {
        int zq = t >> 3, jj = t & 7;
        float s = 0.f;
        for (int u2 = 0; u2 < 16; u2++)
            #pragma unroll
            for (int rg = 0; rg < 4; rg++)
                s += red[(u2 * 16 + zq * 4 + rg) * 8 + jj];
        g_PF[b * 32 + t] = s;
    }
}

// per-sample assembly: rec + classifier + kld
__global__ void k_asm(const float* __restrict__ weights, const int* __restrict__ labels,
                      const int* __restrict__ groups, const float* __restrict__ lbias) {
    int t = threadIdx.x, b = blockIdx.x * 8 + (t >> 5), z = t & 31;
    int g = groups[b];
    float w = g_w[b * 32 + z];
    float red = -2.f * w * g_PF[b * 32 + z];
    const float* GG = g_GG + g * 1024 + z * 32;
    float vs = 0.f;
    #pragma unroll
    for (int k = 0; k < 32; k++) vs += GG[k] * __shfl_sync(0xffffffffu, w, k);
    red += w * vs;
    #pragma unroll
    for (int o = 16; o > 0; o >>= 1) red += __shfl_xor_sync(0xffffffffu, red, o);
    if (z == 0) {
        float rec = (g_s2[b] + red) * (1.f / 65536.f);
        float l0 = g_zs2[b * 32 + 0] + lbias[0];
        float l1 = g_zs2[b * 32 + 1] + lbias[1];
        float l2 = g_zs2[b * 32 + 2] + lbias[2];
        float l3 = 1.f + lbias[3];
        float m = fmaxf(fmaxf(l0, l1), fmaxf(l2, l3));
        float lse = m + logf(expf(l0 - m) + expf(l1 - m) + expf(l2 - m) + expf(l3 - m));
        int lab = labels[b];
        float ll = (lab == 0 ? l0 : lab == 1 ? l1 : lab == 2 ? l2 : l3) - lse;
        g_perb[b] = rec - weights[b] * ll + g_kld[b];
    }
}

__global__ void k_final(float* out) {
    __shared__ float red[256];
    int t = threadIdx.x;
    red[t] = g_perb[t] + g_perb[t + 256] + g_perb[t + 512] + g_perb[t + 768];
    __syncthreads();
    for (int o = 128; o > 0; o >>= 1) {
        if (t < o) red[t] += red[t + o];
        __syncthreads();
    }
    if (t == 0) out[0] = red[0] * (1.f / 1024.f) + g_varloss;
}

extern "C" void kernel_launch(void* const* d_in, const int* in_sizes, int n_in,
                              void* d_out, int out_size) {
    const float* feat    = (const float*)d_in[0];
    const int*   labels  = (const int*)d_in[1];
    const int*   groups  = (const int*)d_in[2];
    const float* weights = (const float*)d_in[3];
    const float* noise   = (const float*)d_in[4];
    const float* ge      = (const float*)d_in[5];
    const float* W1      = (const float*)d_in[6];
    const float* b1      = (const float*)d_in[7];
    const float* W2      = (const float*)d_in[8];
    const float* b2      = (const float*)d_in[9];
    const float* ff      = (const float*)d_in[10];
    const float* r1      = (const float*)d_in[11];
    const float* r2      = (const float*)d_in[12];
    const float* linW    = (const float*)d_in[13];
    const float* linb    = (const float*)d_in[14];
    const float* lbias   = (const float*)d_in[15];
    float* out = (float*)d_out;

    cudaFuncSetAttribute(k_P, cudaFuncAttributeMaxDynamicSharedMemorySize, 86000);

    k_sp<<<256, 256>>>(ff, r1, r2);
    k_gram<<<16, 256>>>();
    k_varloss<<<1, 256>>>();
    k_gemm<<<dim3(KC, 8), 128>>>(feat, W1, W2);
    k_P<<<BATCH, 256, (17024 + 1056 + 1056 + 2048) * 4>>>(feat, groups);
    k_reduce<<<260, 256>>>();
    k_vae<<<128, 256>>>(W1, W2, b1, b2, ge, groups, noise, linW, linb);
    k_asm<<<128, 256>>>(weights, labels, groups, lbias);
    k_final<<<1, 256>>>(out);
}

// round 3
// speedup vs baseline: 1.0056x; 1.0056x over previous
#include <cuda_runtime.h>
#include <math.h>

#define BATCH 1024
#define NFEAT 65536
#define ZD 32
#define NG 16
#define NF 64
#define NR 32
#define KC 256          // split-K chunks for the big GEMM
#define KLEN 256        // NFEAT / KC

typedef unsigned long long ull;

__device__ float g_zpart[KC * BATCH * 64];   // 67 MB split-K partials
__device__ float g_s2part[KC * BATCH];
__device__ float g_zraw[BATCH * 64];
__device__ float g_s2[BATCH];
__device__ float g_spF[NG * ZD * NF];
__device__ float g_spR1[NG * ZD * NR];
__device__ float g_spR2[NG * ZD * NR];
__device__ float g_GG[NG * ZD * ZD];
__device__ float g_w[BATCH * ZD];
__device__ float g_zs2[BATCH * ZD];
__device__ float g_kld[BATCH];
__device__ float g_PFp[2 * BATCH * ZD];      // two halves per b
__device__ float g_perb[BATCH];
__device__ float g_varloss;

static __device__ __forceinline__ float softplusf(float x) {
    return fmaxf(x, 0.f) + log1pf(expf(-fabsf(x)));
}
static __device__ __forceinline__ ull pk2(float lo, float hi) {
    ull r; asm("mov.b64 %0, {%1,%2};" : "=l"(r) : "f"(lo), "f"(hi)); return r;
}
static __device__ __forceinline__ void upk2(ull v, float& lo, float& hi) {
    asm("mov.b64 {%0,%1}, %2;" : "=f"(lo), "=f"(hi) : "l"(v));
}
static __device__ __forceinline__ void fma2(ull& d, ull a, ull b) {
    asm("fma.rn.f32x2 %0, %1, %2, %0;" : "+l"(d) : "l"(a), "l"(b));
}

// ---------------- softplus of factor tensors ----------------
__global__ void k_sp(const float* __restrict__ ff, const float* __restrict__ r1,
                     const float* __restrict__ r2) {
    int i = blockIdx.x * 256 + threadIdx.x;
    const int nF = NG * ZD * NF, nR = NG * ZD * NR;
    if (i < nF) g_spF[i] = softplusf(ff[i]);
    else if (i < nF + nR) g_spR1[i - nF] = softplusf(r1[i - nF]);
    else if (i < nF + 2 * nR) g_spR2[i - nF - nR] = softplusf(r2[i - nF - nR]);
}

// ---------------- per-group Gram products GG = Gf .* G1 .* G2 ----------------
__global__ void k_gram() {
    __shared__ float s1[ZD * NR], s2m[ZD * NR], sf[ZD * NF];
    int g = blockIdx.x, t = threadIdx.x;
    for (int i = t; i < ZD * NR; i += 256) {
        s1[i] = g_spR1[g * ZD * NR + i];
        s2m[i] = g_spR2[g * ZD * NR + i];
    }
    for (int i = t; i < ZD * NF; i += 256) sf[i] = g_spF[g * ZD * NF + i];
    __syncthreads();
    for (int q = t; q < ZD * ZD; q += 256) {
        int z = q >> 5, z2 = q & 31;
        float a = 0.f, b = 0.f, c = 0.f;
        #pragma unroll
        for (int r = 0; r < NR; r++) {
            a += s1[z * NR + r] * s1[z2 * NR + r];
            b += s2m[z * NR + r] * s2m[z2 * NR + r];
        }
        #pragma unroll
        for (int f = 0; f < NF; f++) c += sf[z * NF + f] * sf[z2 * NF + f];
        g_GG[g * ZD * ZD + q] = a * b * c;
    }
}

// ---------------- freq_loss + roi_loss ----------------
__global__ void k_varloss() {
    __shared__ float rf[256], rr[256];
    int t = threadIdx.x;
    float af = 0.f, ar = 0.f;
    for (int idx = t; idx < 4096; idx += 256) {
        float s = 0.f, ss = 0.f;
        if (idx < 2048) {
            #pragma unroll
            for (int g = 0; g < 16; g++) { float x = g_spF[g * 2048 + idx]; s += x; ss += x * x; }
            af += (ss - s * s * (1.f / 16.f)) * (1.f / 15.f);
        } else if (idx < 3072) {
            int j = idx - 2048;
            #pragma unroll
            for (int g = 0; g < 16; g++) { float x = g_spR1[g * 1024 + j]; s += x; ss += x * x; }
            ar += (ss - s * s * (1.f / 16.f)) * (1.f / 15.f);
        } else {
            int j = idx - 3072;
            #pragma unroll
            for (int g = 0; g < 16; g++) { float x = g_spR2[g * 1024 + j]; s += x; ss += x * x; }
            ar += (ss - s * s * (1.f / 16.f)) * (1.f / 15.f);
        }
    }
    rf[t] = af; rr[t] = ar;
    __syncthreads();
    for (int o = 128; o > 0; o >>= 1) {
        if (t < o) { rf[t] += rf[t + o]; rr[t] += rr[t + o]; }
        __syncthreads();
    }
    if (t == 0) g_varloss = rf[0] * (1.f / 64.f) + rr[0] * (1.f / 32.f);
}

// ---------------- big GEMM with f32x2 packed FMA ----------------
// grid (KC=256, 8 btiles), 256 threads, BM=128 BN=64 BK=32
// thread tile: 8 rows (4 packed pairs) x 4 cols, FMA2 packs along rows.
__global__ void __launch_bounds__(256) k_gemm(const float* __restrict__ feat,
                                              const float* __restrict__ W1,
                                              const float* __restrict__ W2) {
    __shared__ float As[32][130];      // [k][b]
    __shared__ float Bs[32][68];       // [k][n]
    __shared__ float s2s[128][2];
    int t = threadIdx.x;
    int kc = blockIdx.x, bt = blockIdx.y;
    int r = t >> 1, kh = (t & 1) * 16;
    const float* fb = feat + ((size_t)(bt * 128 + r)) * NFEAT + kc * KLEN + kh;
    int rb2 = (t & 15) * 2, c0 = (t >> 4) * 4;

    ull acc[4][4];
    #pragma unroll
    for (int p = 0; p < 4; p++)
        #pragma unroll
        for (int j = 0; j < 4; j++) acc[p][j] = 0ull;
    float sq = 0.f;

    float4 ra[4], rbv[2];
    #pragma unroll
    for (int i = 0; i < 4; i++) ra[i] = *(const float4*)(fb + i * 4);
    #pragma unroll
    for (int i = 0; i < 2; i++) {
        int idx = t * 2 + i; int k = idx >> 4; int c4 = idx & 15;
        size_t row = (size_t)kc * KLEN + k;
        rbv[i] = (c4 < 8) ? *(const float4*)(W1 + row * 32 + c4 * 4)
                          : *(const float4*)(W2 + row * 32 + (c4 - 8) * 4);
    }

    for (int kt = 0; kt < KLEN / 32; kt++) {
        #pragma unroll
        for (int i = 0; i < 4; i++) {
            As[kh + 4 * i + 0][r] = ra[i].x;
            As[kh + 4 * i + 1][r] = ra[i].y;
            As[kh + 4 * i + 2][r] = ra[i].z;
            As[kh + 4 * i + 3][r] = ra[i].w;
            sq += ra[i].x * ra[i].x + ra[i].y * ra[i].y + ra[i].z * ra[i].z + ra[i].w * ra[i].w;
        }
        #pragma unroll
        for (int i = 0; i < 2; i++) {
            int idx = t * 2 + i; int k = idx >> 4; int c4 = idx & 15;
            *(float4*)&Bs[k][c4 * 4] = rbv[i];
        }
        __syncthreads();
        if (kt < KLEN / 32 - 1) {
            #pragma unroll
            for (int i = 0; i < 4; i++)
                ra[i] = *(const float4*)(fb + (kt + 1) * 32 + i * 4);
            #pragma unroll
            for (int i = 0; i < 2; i++) {
                int idx = t * 2 + i; int k = idx >> 4; int c4 = idx & 15;
                size_t row = (size_t)kc * KLEN + (kt + 1) * 32 + k;
                rbv[i] = (c4 < 8) ? *(const float4*)(W1 + row * 32 + c4 * 4)
                                  : *(const float4*)(W2 + row * 32 + (c4 - 8) * 4);
            }
        }
        #pragma unroll
        for (int k = 0; k < 32; k++) {
            ull a0 = *(const ull*)&As[k][rb2];
            ull a1 = *(const ull*)&As[k][32 + rb2];
            ull a2 = *(const ull*)&As[k][64 + rb2];
            ull a3 = *(const ull*)&As[k][96 + rb2];
            float4 bq = *(const float4*)&Bs[k][c0];
            ull b0 = pk2(bq.x, bq.x), b1 = pk2(bq.y, bq.y);
            ull b2 = pk2(bq.z, bq.z), b3 = pk2(bq.w, bq.w);
            fma2(acc[0][0], a0, b0); fma2(acc[0][1], a0, b1);
            fma2(acc[0][2], a0, b2); fma2(acc[0][3], a0, b3);
            fma2(acc[1][0], a1, b0); fma2(acc[1][1], a1, b1);
            fma2(acc[1][2], a1, b2); fma2(acc[1][3], a1, b3);
            fma2(acc[2][0], a2, b0); fma2(acc[2][1], a2, b1);
            fma2(acc[2][2], a2, b2); fma2(acc[2][3], a2, b3);
            fma2(acc[3][0], a3, b0); fma2(acc[3][1], a3, b1);
            fma2(acc[3][2], a3, b2); fma2(acc[3][3], a3, b3);
        }
        __syncthreads();
    }

    float* zp = g_zpart + ((size_t)kc * BATCH + bt * 128) * 64;
    #pragma unroll
    for (int p = 0; p < 4; p++) {
        float lo[4], hi[4];
        #pragma unroll
        for (int j = 0; j < 4; j++) upk2(acc[p][j], lo[j], hi[j]);
        int rr2 = 32 * p + rb2;
        *(float4*)&zp[(size_t)rr2 * 64 + c0] = make_float4(lo[0], lo[1], lo[2], lo[3]);
        *(float4*)&zp[(size_t)(rr2 + 1) * 64 + c0] = make_float4(hi[0], hi[1], hi[2], hi[3]);
    }
    s2s[r][t & 1] = sq;
    __syncthreads();
    if (t < 128) g_s2part[kc * BATCH + bt * 128 + t] = s2s[t][0] + s2s[t][1];
}

// ---------------- reduce split-K partials ----------------
__global__ void k_reduce() {
    int i = blockIdx.x * 256 + threadIdx.x;
    if (i < BATCH * 64) {
        float s = 0.f;
        for (int kc = 0; kc < KC; kc++) s += g_zpart[(size_t)kc * BATCH * 64 + i];
        g_zraw[i] = s;
    } else if (i < BATCH * 64 + BATCH) {
        int b = i - BATCH * 64;
        float s = 0.f;
        for (int kc = 0; kc < KC; kc++) s += g_s2part[kc * BATCH + b];
        g_s2[b] = s;
    }
}

// ---------------- VAE head ----------------
__global__ void k_vae(const float* __restrict__ W1, const float* __restrict__ W2,
                      const float* __restrict__ b1, const float* __restrict__ b2,
                      const float* __restrict__ ge, const int* __restrict__ groups,
                      const float* __restrict__ noise, const float* __restrict__ linW,
                      const float* __restrict__ linb) {
    int t = threadIdx.x, b = blockIdx.x * 8 + (t >> 5), z = t & 31;
    int g = groups[b];
    float e0 = ge[g * 2], e1 = ge[g * 2 + 1];
    float mu = g_zraw[b * 64 + z] + b1[z] + e0 * W1[65536 * 32 + z] + e1 * W1[65537 * 32 + z];
    float ls = g_zraw[b * 64 + 32 + z] + b2[z] + e0 * W2[65536 * 32 + z] + e1 * W2[65537 * 32 + z];
    float sig = 1e-6f + expf(ls);
    float kt = -logf(sig) + 0.5f * (sig * sig + mu * mu - 1.f);
    #pragma unroll
    for (int o = 16; o > 0; o >>= 1) kt += __shfl_xor_sync(0xffffffffu, kt, o);
    if (z == 0) g_kld[b] = kt;
    float zs = mu + sig * noise[b * 32 + z];
    float acc = linb[z];
    #pragma unroll
    for (int k = 0; k < 32; k++)
        acc += __shfl_sync(0xffffffffu, zs, k) * linW[k * 32 + z];
    g_zs2[b * 32 + z] = acc;
    g_w[b * 32 + z] = softplusf(acc);
}

// ---------------- PF core with f32x2 ----------------
// 2048 CTAs: (b, half). Each handles 32 freqs in 2 iters of 16 staged tiles.
// M stored column-major [s][r] stride 34 so row-pairs are 8B LDS.64.
extern __shared__ float sm[];
__global__ void __launch_bounds__(256) k_P(const float* __restrict__ feat,
                                           const int* __restrict__ groups) {
    float* Ms = sm;                       // 16 tiles x 32*34
    float* R1 = sm + 17408;               // [32][34]
    float* R2 = R1 + 1088;                // [32][34]
    float* Fp = R2 + 1088;                // [32][64]
    int t = threadIdx.x;
    int b = blockIdx.x >> 1, half = blockIdx.x & 1;
    int g = groups[b];
    for (int i = t; i < ZD * NR; i += 256) {
        int z = i >> 5, r = i & 31;
        R1[z * 34 + r] = g_spR1[g * 1024 + i];
        R2[z * 34 + r] = g_spR2[g * 1024 + i];
    }
    for (int i = t; i < ZD * NF; i += 256) Fp[i] = g_spF[g * 2048 + i];
    int u = t >> 4, v = t & 15;
    int r0 = (v & 3) * 8, z0 = (v >> 2) * 8;
    float accA[8];
    #pragma unroll
    for (int j = 0; j < 8; j++) accA[j] = 0.f;
    const float4* fb4 = (const float4*)(feat + (size_t)b * NFEAT + half * 32768);
    int wr1 = t >> 3, wr2 = (t & 7) * 4;

    for (int it = 0; it < 2; it++) {
        __syncthreads();
        #pragma unroll
        for (int j = 0; j < 16; j++) {
            float4 vv = fb4[(it * 16 + j) * 256 + t];
            float* Mj = Ms + j * 1088;
            Mj[(wr2 + 0) * 34 + wr1] = vv.x;
            Mj[(wr2 + 1) * 34 + wr1] = vv.y;
            Mj[(wr2 + 2) * 34 + wr1] = vv.z;
            Mj[(wr2 + 3) * 34 + wr1] = vv.w;
        }
        __syncthreads();
        const float* M = Ms + u * 1088;
        ull T[4][8];
        #pragma unroll
        for (int q = 0; q < 4; q++)
            #pragma unroll
            for (int j = 0; j < 8; j++) T[q][j] = 0ull;
        #pragma unroll 4
        for (int s = 0; s < 32; s++) {
            ull a[4];
            #pragma unroll
            for (int q = 0; q < 4; q++) a[q] = *(const ull*)&M[s * 34 + r0 + 2 * q];
            ull bb[8];
            #pragma unroll
            for (int j = 0; j < 8; j++) {
                float bv = R2[(z0 + j) * 34 + s];
                bb[j] = pk2(bv, bv);
            }
            #pragma unroll
            for (int q = 0; q < 4; q++)
                #pragma unroll
                for (int j = 0; j < 8; j++) fma2(T[q][j], a[q], bb[j]);
        }
        int f = half * 32 + it * 16 + u;
        #pragma unroll
        for (int j = 0; j < 8; j++) {
            ull pp = 0ull;
            #pragma unroll
            for (int q = 0; q < 4; q++)
                fma2(pp, *(const ull*)&R1[(z0 + j) * 34 + r0 + 2 * q], T[q][j]);
            float plo, phi; upk2(pp, plo, phi);
            accA[j] += Fp[(z0 + j) * 64 + f] * (plo + phi);
        }
    }
    __syncthreads();
    float* red = sm;
    #pragma unroll
    for (int j = 0; j < 8; j++) red[t * 8 + j] = accA[j];
    __syncthreads();
    if (t < 32) {
        int zq = t >> 3, jj = t & 7;
        float s = 0.f;
        for (int u2 = 0; u2 < 16; u2++)
            #pragma unroll
            for (int rg = 0; rg < 4; rg++)
                s += red[(u2 * 16 + zq * 4 + rg) * 8 + jj];
        g_PFp[blockIdx.x * 32 + t] = s;
    }
}

// ---------------- per-sample assembly ----------------
__global__ void k_asm(const float* __restrict__ weights, const int* __restrict__ labels,
                      const int* __restrict__ groups, const float* __restrict__ lbias) {
    int t = threadIdx.x, b = blockIdx.x * 8 + (t >> 5), z = t & 31;
    int g = groups[b];
    float w = g_w[b * 32 + z];
    float pf = g_PFp[(b * 2) * 32 + z] + g_PFp[(b * 2 + 1) * 32 + z];
    float red = -2.f * w * pf;
    const float* GG = g_GG + g * 1024 + z * 32;
    float vs = 0.f;
    #pragma unroll
    for (int k = 0; k < 32; k++) vs += GG[k] * __shfl_sync(0xffffffffu, w, k);
    red += w * vs;
    #pragma unroll
    for (int o = 16; o > 0; o >>= 1) red += __shfl_xor_sync(0xffffffffu, red, o);
    if (z == 0) {
        float rec = (g_s2[b] + red) * (1.f / 65536.f);
        float l0 = g_zs2[b * 32 + 0] + lbias[0];
        float l1 = g_zs2[b * 32 + 1] + lbias[1];
        float l2 = g_zs2[b * 32 + 2] + lbias[2];
        float l3 = 1.f + lbias[3];
        float m = fmaxf(fmaxf(l0, l1), fmaxf(l2, l3));
        float lse = m + logf(expf(l0 - m) + expf(l1 - m) + expf(l2 - m) + expf(l3 - m));
        int lab = labels[b];
        float ll = (lab == 0 ? l0 : lab == 1 ? l1 : lab == 2 ? l2 : l3) - lse;
        g_perb[b] = rec - weights[b] * ll + g_kld[b];
    }
}

__global__ void k_final(float* out) {
    __shared__ float red[256];
    int t = threadIdx.x;
    red[t] = g_perb[t] + g_perb[t + 256] + g_perb[t + 512] + g_perb[t + 768];
    __syncthreads();
    for (int o = 128; o > 0; o >>= 1) {
        if (t < o) red[t] += red[t + o];
        __syncthreads();
    }
    if (t == 0) out[0] = red[0] * (1.f / 1024.f) + g_varloss;
}

extern "C" void kernel_launch(void* const* d_in, const int* in_sizes, int n_in,
                              void* d_out, int out_size) {
    const float* feat    = (const float*)d_in[0];
    const int*   labels  = (const int*)d_in[1];
    const int*   groups  = (const int*)d_in[2];
    const float* weights = (const float*)d_in[3];
    const float* noise   = (const float*)d_in[4];
    const float* ge      = (const float*)d_in[5];
    const float* W1      = (const float*)d_in[6];
    const float* b1      = (const float*)d_in[7];
    const float* W2      = (const float*)d_in[8];
    const float* b2      = (const float*)d_in[9];
    const float* ff      = (const float*)d_in[10];
    const float* r1      = (const float*)d_in[11];
    const float* r2      = (const float*)d_in[12];
    const float* linW    = (const float*)d_in[13];
    const float* linb    = (const float*)d_in[14];
    const float* lbias   = (const float*)d_in[15];
    float* out = (float*)d_out;

    cudaFuncSetAttribute(k_P, cudaFuncAttributeMaxDynamicSharedMemorySize, 90000);

    k_sp<<<256, 256>>>(ff, r1, r2);
    k_gram<<<16, 256>>>();
    k_varloss<<<1, 256>>>();
    k_gemm<<<dim3(KC, 8), 256>>>(feat, W1, W2);
    k_P<<<2048, 256, (17408 + 1088 + 1088 + 2048) * 4>>>(feat, groups);
    k_reduce<<<260, 256>>>();
    k_vae<<<128, 256>>>(W1, W2, b1, b2, ge, groups, noise, linW, linb);
    k_asm<<<128, 256>>>(weights, labels, groups, lbias);
    k_final<<<1, 256>>>(out);
}

// round 4
// speedup vs baseline: 1.4594x; 1.4512x over previous
#include <cuda_runtime.h>
#include <cuda_bf16.h>
#include <math.h>

#define BATCH 1024
#define NFEAT 65536
#define ZD 32
#define NG 16
#define NF 64
#define NR 32
#define KCS 32            // split-K for the fused GEMM

typedef unsigned int u32;

__device__ float g_zpart[KCS * BATCH * 96];     // 12.6 MB split-K partials
__device__ float g_s2part[KCS * BATCH];
__device__ float g_zraw[BATCH * 64];
__device__ float g_PF[BATCH * ZD];
__device__ float g_s2[BATCH];
__device__ float g_spF[NG * ZD * NF];
__device__ float g_spR1[NG * ZD * NR];
__device__ float g_spR2[NG * ZD * NR];
__device__ float g_GG[NG * ZD * ZD];
__device__ float g_w[BATCH * ZD];
__device__ float g_zs2[BATCH * ZD];
__device__ float g_kld[BATCH];
__device__ float g_perb[BATCH];
__device__ float g_varloss;
__device__ __nv_bfloat16 g_WcT[64 * NFEAT];     // [n][k] transposed bf16 W1|W2
__device__ int g_sIdx[BATCH];
__device__ int g_gcnt[NG];
__device__ int g_goff[NG];

static __device__ __forceinline__ float softplusf(float x) {
    return fmaxf(x, 0.f) + log1pf(expf(-fabsf(x)));
}
static __device__ __forceinline__ u32 cvt2(float a, float b) {
    __nv_bfloat162 h = __floats2bfloat162_rn(a, b);
    return *reinterpret_cast<u32*>(&h);
}
static __device__ __forceinline__ void ldsm4(u32& r0, u32& r1, u32& r2, u32& r3, u32 addr) {
    asm volatile("ldmatrix.sync.aligned.m8n8.x4.shared.b16 {%0,%1,%2,%3}, [%4];"
                 : "=r"(r0), "=r"(r1), "=r"(r2), "=r"(r3) : "r"(addr));
}
static __device__ __forceinline__ void ldsm2(u32& r0, u32& r1, u32 addr) {
    asm volatile("ldmatrix.sync.aligned.m8n8.x2.shared.b16 {%0,%1}, [%2];"
                 : "=r"(r0), "=r"(r1) : "r"(addr));
}
static __device__ __forceinline__ void mma16816(float* c, u32 a0, u32 a1, u32 a2, u32 a3,
                                                u32 b0, u32 b1) {
    asm volatile(
        "mma.sync.aligned.m16n8k16.row.col.f32.bf16.bf16.f32 "
        "{%0,%1,%2,%3}, {%4,%5,%6,%7}, {%8,%9}, {%0,%1,%2,%3};"
        : "+f"(c[0]), "+f"(c[1]), "+f"(c[2]), "+f"(c[3])
        : "r"(a0), "r"(a1), "r"(a2), "r"(a3), "r"(b0), "r"(b1));
}

// ---------------- softplus of factor tensors ----------------
__global__ void k_sp(const float* __restrict__ ff, const float* __restrict__ r1,
                     const float* __restrict__ r2) {
    int i = blockIdx.x * 256 + threadIdx.x;
    const int nF = NG * ZD * NF, nR = NG * ZD * NR;
    if (i < nF) g_spF[i] = softplusf(ff[i]);
    else if (i < nF + nR) g_spR1[i - nF] = softplusf(r1[i - nF]);
    else if (i < nF + 2 * nR) g_spR2[i - nF - nR] = softplusf(r2[i - nF - nR]);
}

// ---------------- per-group Gram products ----------------
__global__ void k_gram() {
    __shared__ float s1[ZD * NR], s2m[ZD * NR], sf[ZD * NF];
    int g = blockIdx.x, t = threadIdx.x;
    for (int i = t; i < ZD * NR; i += 256) {
        s1[i] = g_spR1[g * ZD * NR + i];
        s2m[i] = g_spR2[g * ZD * NR + i];
    }
    for (int i = t; i < ZD * NF; i += 256) sf[i] = g_spF[g * ZD * NF + i];
    __syncthreads();
    for (int q = t; q < ZD * ZD; q += 256) {
        int z = q >> 5, z2 = q & 31;
        float a = 0.f, b = 0.f, c = 0.f;
        #pragma unroll
        for (int r = 0; r < NR; r++) {
            a += s1[z * NR + r] * s1[z2 * NR + r];
            b += s2m[z * NR + r] * s2m[z2 * NR + r];
        }
        #pragma unroll
        for (int f = 0; f < NF; f++) c += sf[z * NF + f] * sf[z2 * NF + f];
        g_GG[g * ZD * ZD + q] = a * b * c;
    }
}

// ---------------- freq_loss + roi_loss ----------------
__global__ void k_varloss() {
    __shared__ float rf[256], rr[256];
    int t = threadIdx.x;
    float af = 0.f, ar = 0.f;
    for (int idx = t; idx < 4096; idx += 256) {
        float s = 0.f, ss = 0.f;
        if (idx < 2048) {
            #pragma unroll
            for (int g = 0; g < 16; g++) { float x = g_spF[g * 2048 + idx]; s += x; ss += x * x; }
            af += (ss - s * s * (1.f / 16.f)) * (1.f / 15.f);
        } else if (idx < 3072) {
            int j = idx - 2048;
            #pragma unroll
            for (int g = 0; g < 16; g++) { float x = g_spR1[g * 1024 + j]; s += x; ss += x * x; }
            ar += (ss - s * s * (1.f / 16.f)) * (1.f / 15.f);
        } else {
            int j = idx - 3072;
            #pragma unroll
            for (int g = 0; g < 16; g++) { float x = g_spR2[g * 1024 + j]; s += x; ss += x * x; }
            ar += (ss - s * s * (1.f / 16.f)) * (1.f / 15.f);
        }
    }
    rf[t] = af; rr[t] = ar;
    __syncthreads();
    for (int o = 128; o > 0; o >>= 1) {
        if (t < o) { rf[t] += rf[t + o]; rr[t] += rr[t + o]; }
        __syncthreads();
    }
    if (t == 0) g_varloss = rf[0] * (1.f / 64.f) + rr[0] * (1.f / 32.f);
}

// ---------------- deterministic counting sort by group ----------------
__global__ void k_sort(const int* __restrict__ groups) {
    __shared__ int sg[1024];
    __shared__ int cnt[16], off[16];
    int t = threadIdx.x;
    sg[t] = groups[t];
    if (t < 16) cnt[t] = 0;
    __syncthreads();
    atomicAdd(&cnt[sg[t]], 1);
    __syncthreads();
    if (t == 0) {
        int s = 0;
        for (int i = 0; i < 16; i++) { off[i] = s; s += cnt[i]; }
    }
    __syncthreads();
    int g = sg[t], rank = 0;
    for (int j = 0; j < 1024; j++)
        if (j < t && sg[j] == g) rank++;
    g_sIdx[off[g] + rank] = t;
    if (t < 16) { g_gcnt[t] = cnt[t]; g_goff[t] = off[t]; }
}

// ---------------- transpose+convert W1|W2 -> WcT bf16 [64 n][65536 k] ----------------
__global__ void k_wcT(const float* __restrict__ W1, const float* __restrict__ W2) {
    __shared__ float tile[32][33];
    int w = blockIdx.y;
    int k0 = blockIdx.x * 32;
    int tx = threadIdx.x, ty = threadIdx.y;
    const float* W = w ? W2 : W1;
    tile[ty][tx] = W[(size_t)(k0 + ty) * 32 + tx];
    __syncthreads();
    g_WcT[(size_t)(w * 32 + ty) * NFEAT + k0 + tx] = __float2bfloat16_rn(tile[tx][ty]);
}

// ---------------- fused tensor-core GEMM ----------------
// grid (48 mtiles = 16 groups x 3, KCS kc). CTA: 64 gathered rows x 96 cols x 2048 K.
// cols 0..63 = WcT (encoder), 64..95 = on-the-fly WP (rec-loss core). Fuses s2.
__global__ void __launch_bounds__(256) g_mm(const float* __restrict__ feat) {
    __shared__ __nv_bfloat16 As[64][72];
    __shared__ __nv_bfloat16 Bs[96][72];
    __shared__ float sF[ZD * NF];
    __shared__ float sR1[ZD * NR];
    __shared__ float sR2[ZD * NR];
    __shared__ int sIdx[64];

    int mt = blockIdx.x, kc = blockIdx.y;
    int g = mt / 3, ti = mt % 3;
    int nb = g_gcnt[g];
    int m0 = ti * 64;
    if (m0 >= nb) return;
    int goff = g_goff[g];
    int vr = nb - m0; if (vr > 64) vr = 64;
    int t = threadIdx.x;

    for (int i = t; i < ZD * NF; i += 256) sF[i] = g_spF[g * ZD * NF + i];
    for (int i = t; i < ZD * NR; i += 256) {
        sR1[i] = g_spR1[g * ZD * NR + i];
        sR2[i] = g_spR2[g * ZD * NR + i];
    }
    if (t < 64) sIdx[t] = (t < vr) ? g_sIdx[goff + m0 + t] : 0;
    __syncthreads();

    int lane = t & 31, wid = t >> 5;
    int wm = wid & 1, wn = wid >> 1;          // warp tile: rows wm*32+32, cols wn*24+24
    float acc[2][3][4];
    #pragma unroll
    for (int mf = 0; mf < 2; mf++)
        #pragma unroll
        for (int nf = 0; nf < 3; nf++)
            #pragma unroll
            for (int q = 0; q < 4; q++) acc[mf][nf][q] = 0.f;

    int ar = t >> 2, aq = t & 3;
    bool aval = ar < vr;
    const float* arow = feat + (size_t)sIdx[ar] * NFEAT;
    float sq = 0.f;

    u32 sA = (u32)__cvta_generic_to_shared(&As[0][0]);
    u32 sB = (u32)__cvta_generic_to_shared(&Bs[0][0]);
    int kbase0 = kc * 2048;

    for (int kt = 0; kt < 32; kt++) {
        int kb = kbase0 + kt * 64;
        // --- stage A (fp32 -> bf16, fused s2) ---
        {
            uint4 o0 = {0, 0, 0, 0}, o1 = {0, 0, 0, 0};
            if (aval) {
                const float4* src = (const float4*)(arow + kb + aq * 16);
                float4 v0 = src[0], v1 = src[1], v2 = src[2], v3 = src[3];
                sq += v0.x * v0.x + v0.y * v0.y + v0.z * v0.z + v0.w * v0.w;
                sq += v1.x * v1.x + v1.y * v1.y + v1.z * v1.z + v1.w * v1.w;
                sq += v2.x * v2.x + v2.y * v2.y + v2.z * v2.z + v2.w * v2.w;
                sq += v3.x * v3.x + v3.y * v3.y + v3.z * v3.z + v3.w * v3.w;
                o0.x = cvt2(v0.x, v0.y); o0.y = cvt2(v0.z, v0.w);
                o0.z = cvt2(v1.x, v1.y); o0.w = cvt2(v1.z, v1.w);
                o1.x = cvt2(v2.x, v2.y); o1.y = cvt2(v2.z, v2.w);
                o1.z = cvt2(v3.x, v3.y); o1.w = cvt2(v3.z, v3.w);
            }
            *(uint4*)&As[ar][aq * 16] = o0;
            *(uint4*)&As[ar][aq * 16 + 8] = o1;
        }
        // --- stage B rows 0..63 from WcT ---
        {
            int n = t >> 2, c = (t & 3) * 2;
            const uint4* src = (const uint4*)(g_WcT + (size_t)n * NFEAT + kb);
            uint4* dst = (uint4*)&Bs[n][0];
            dst[c] = src[c];
            dst[c + 1] = src[c + 1];
        }
        // --- stage B rows 64..95: WP on the fly ---
        {
            int z = t >> 3, i0 = (t & 7) * 8;
            int f = kb >> 10, r0 = (kb >> 5) & 31;
            float c0 = sF[z * NF + f] * sR1[z * NR + r0 + (i0 >> 5)];
            int s0 = i0 & 31;
            u32* dst = (u32*)&Bs[64 + z][i0];
            #pragma unroll
            for (int j = 0; j < 4; j++)
                dst[j] = cvt2(c0 * sR2[z * NR + s0 + 2 * j],
                              c0 * sR2[z * NR + s0 + 2 * j + 1]);
        }
        __syncthreads();
        // --- mma ---
        #pragma unroll
        for (int ks = 0; ks < 4; ks++) {
            int kbs = ks * 16;
            u32 b0[3], b1[3];
            #pragma unroll
            for (int nf = 0; nf < 3; nf++) {
                int n = wn * 24 + nf * 8 + (lane & 7);
                u32 addr = sB + (u32)(n * 72 + kbs + ((lane >> 3) & 1) * 8) * 2;
                ldsm2(b0[nf], b1[nf], addr);
            }
            #pragma unroll
            for (int mf = 0; mf < 2; mf++) {
                int row = wm * 32 + mf * 16 + (lane & 15);
                u32 addr = sA + (u32)(row * 72 + kbs + (lane >> 4) * 8) * 2;
                u32 a0, a1, a2, a3;
                ldsm4(a0, a1, a2, a3, addr);
                #pragma unroll
                for (int nf = 0; nf < 3; nf++)
                    mma16816(acc[mf][nf], a0, a1, a2, a3, b0[nf], b1[nf]);
            }
        }
        __syncthreads();
    }
    // s2 partial (4 threads per row)
    sq += __shfl_down_sync(0xffffffffu, sq, 2, 4);
    sq += __shfl_down_sync(0xffffffffu, sq, 1, 4);
    if (aq == 0 && aval) g_s2part[kc * BATCH + goff + m0 + ar] = sq;
    // epilogue: scatter fp32 partials
    #pragma unroll
    for (int mf = 0; mf < 2; mf++) {
        #pragma unroll
        for (int half = 0; half < 2; half++) {
            int r = wm * 32 + mf * 16 + (lane >> 2) + half * 8;
            if (r < vr) {
                int p = goff + m0 + r;
                float* dst = g_zpart + ((size_t)kc * BATCH + p) * 96;
                #pragma unroll
                for (int nf = 0; nf < 3; nf++) {
                    int ncol = wn * 24 + nf * 8 + (lane & 3) * 2;
                    float2 v = half ? make_float2(acc[mf][nf][2], acc[mf][nf][3])
                                    : make_float2(acc[mf][nf][0], acc[mf][nf][1]);
                    *(float2*)(dst + ncol) = v;
                }
            }
        }
    }
}

// ---------------- reduce split-K partials; scatter sorted->original ----------------
__global__ void k_red() {
    int i = blockIdx.x * 256 + threadIdx.x;
    if (i < BATCH * 96) {
        int p = i / 96, n = i - p * 96;
        float s = 0.f;
        for (int kc = 0; kc < KCS; kc++) s += g_zpart[((size_t)kc * BATCH + p) * 96 + n];
        int b = g_sIdx[p];
        if (n < 64) g_zraw[b * 64 + n] = s;
        else g_PF[b * 32 + n - 64] = s;
    } else if (i < BATCH * 96 + BATCH) {
        int p = i - BATCH * 96;
        float s = 0.f;
        for (int kc = 0; kc < KCS; kc++) s += g_s2part[kc * BATCH + p];
        g_s2[g_sIdx[p]] = s;
    }
}

// ---------------- VAE head ----------------
__global__ void k_vae(const float* __restrict__ W1, const float* __restrict__ W2,
                      const float* __restrict__ b1, const float* __restrict__ b2,
                      const float* __restrict__ ge, const int* __restrict__ groups,
                      const float* __restrict__ noise, const float* __restrict__ linW,
                      const float* __restrict__ linb) {
    int t = threadIdx.x, b = blockIdx.x * 8 + (t >> 5), z = t & 31;
    int g = groups[b];
    float e0 = ge[g * 2], e1 = ge[g * 2 + 1];
    float mu = g_zraw[b * 64 + z] + b1[z] + e0 * W1[65536 * 32 + z] + e1 * W1[65537 * 32 + z];
    float ls = g_zraw[b * 64 + 32 + z] + b2[z] + e0 * W2[65536 * 32 + z] + e1 * W2[65537 * 32 + z];
    float sig = 1e-6f + expf(ls);
    float kt = -logf(sig) + 0.5f * (sig * sig + mu * mu - 1.f);
    #pragma unroll
    for (int o = 16; o > 0; o >>= 1) kt += __shfl_xor_sync(0xffffffffu, kt, o);
    if (z == 0) g_kld[b] = kt;
    float zs = mu + sig * noise[b * 32 + z];
    float acc = linb[z];
    #pragma unroll
    for (int k = 0; k < 32; k++)
        acc += __shfl_sync(0xffffffffu, zs, k) * linW[k * 32 + z];
    g_zs2[b * 32 + z] = acc;
    g_w[b * 32 + z] = softplusf(acc);
}

// ---------------- per-sample assembly ----------------
__global__ void k_asm(const float* __restrict__ weights, const int* __restrict__ labels,
                      const int* __restrict__ groups, const float* __restrict__ lbias) {
    int t = threadIdx.x, b = blockIdx.x * 8 + (t >> 5), z = t & 31;
    int g = groups[b];
    float w = g_w[b * 32 + z];
    float red = -2.f * w * g_PF[b * 32 + z];
    const float* GG = g_GG + g * 1024 + z * 32;
    float vs = 0.f;
    #pragma unroll
    for (int k = 0; k < 32; k++) vs += GG[k] * __shfl_sync(0xffffffffu, w, k);
    red += w * vs;
    #pragma unroll
    for (int o = 16; o > 0; o >>= 1) red += __shfl_xor_sync(0xffffffffu, red, o);
    if (z == 0) {
        float rec = (g_s2[b] + red) * (1.f / 65536.f);
        float l0 = g_zs2[b * 32 + 0] + lbias[0];
        float l1 = g_zs2[b * 32 + 1] + lbias[1];
        float l2 = g_zs2[b * 32 + 2] + lbias[2];
        float l3 = 1.f + lbias[3];
        float m = fmaxf(fmaxf(l0, l1), fmaxf(l2, l3));
        float lse = m + logf(expf(l0 - m) + expf(l1 - m) + expf(l2 - m) + expf(l3 - m));
        int lab = labels[b];
        float ll = (lab == 0 ? l0 : lab == 1 ? l1 : lab == 2 ? l2 : l3) - lse;
        g_perb[b] = rec - weights[b] * ll + g_kld[b];
    }
}

__global__ void k_final(float* out) {
    __shared__ float red[256];
    int t = threadIdx.x;
    red[t] = g_perb[t] + g_perb[t + 256] + g_perb[t + 512] + g_perb[t + 768];
    __syncthreads();
    for (int o = 128; o > 0; o >>= 1) {
        if (t < o) red[t] += red[t + o];
        __syncthreads();
    }
    if (t == 0) out[0] = red[0] * (1.f / 1024.f) + g_varloss;
}

extern "C" void kernel_launch(void* const* d_in, const int* in_sizes, int n_in,
                              void* d_out, int out_size) {
    const float* feat    = (const float*)d_in[0];
    const int*   labels  = (const int*)d_in[1];
    const int*   groups  = (const int*)d_in[2];
    const float* weights = (const float*)d_in[3];
    const float* noise   = (const float*)d_in[4];
    const float* ge      = (const float*)d_in[5];
    const float* W1      = (const float*)d_in[6];
    const float* b1      = (const float*)d_in[7];
    const float* W2      = (const float*)d_in[8];
    const float* b2      = (const float*)d_in[9];
    const float* ff      = (const float*)d_in[10];
    const float* r1      = (const float*)d_in[11];
    const float* r2      = (const float*)d_in[12];
    const float* linW    = (const float*)d_in[13];
    const float* linb    = (const float*)d_in[14];
    const float* lbias   = (const float*)d_in[15];
    float* out = (float*)d_out;

    k_sp<<<256, 256>>>(ff, r1, r2);
    k_gram<<<16, 256>>>();
    k_varloss<<<1, 256>>>();
    k_sort<<<1, 1024>>>(groups);
    k_wcT<<<dim3(2048, 2), dim3(32, 32)>>>(W1, W2);
    g_mm<<<dim3(48, KCS), 256>>>(feat);
    k_red<<<388, 256>>>();
    k_vae<<<128, 256>>>(W1, W2, b1, b2, ge, groups, noise, linW, linb);
    k_asm<<<128, 256>>>(weights, labels, groups, lbias);
    k_final<<<1, 256>>>(out);
}

// round 5
// speedup vs baseline: 1.9129x; 1.3107x over previous
#include <cuda_runtime.h>
#include <cuda_bf16.h>
#include <math.h>

#define BATCH 1024
#define NFEAT 65536
#define ZD 32
#define NG 16
#define NF 64
#define NR 32
#define KCS 16            // split-K for the fused GEMM

typedef unsigned int u32;

__device__ float g_zpart[KCS * BATCH * 96];
__device__ float g_s2part[KCS * BATCH];
__device__ float g_zraw[BATCH * 64];
__device__ float g_PF[BATCH * ZD];
__device__ float g_s2[BATCH];
__device__ float g_spF[NG * ZD * NF];
__device__ float g_spR1[NG * ZD * NR];
__device__ float g_spR2[NG * ZD * NR];
__device__ float g_GG[NG * ZD * ZD];
__device__ float g_w[BATCH * ZD];
__device__ float g_zs2[BATCH * ZD];
__device__ float g_kld[BATCH];
__device__ float g_perb[BATCH];
__device__ float g_varloss;
__device__ __nv_bfloat16 g_WcT[64 * NFEAT];     // [n][k] transposed bf16 W1|W2
__device__ int g_sIdx[BATCH];
__device__ int g_gcnt[NG];
__device__ int g_goff[NG];

static __device__ __forceinline__ float softplusf(float x) {
    return fmaxf(x, 0.f) + log1pf(expf(-fabsf(x)));
}
static __device__ __forceinline__ u32 cvt2(float a, float b) {
    __nv_bfloat162 h = __floats2bfloat162_rn(a, b);
    return *reinterpret_cast<u32*>(&h);
}
static __device__ __forceinline__ void ldsm4(u32& r0, u32& r1, u32& r2, u32& r3, u32 addr) {
    asm volatile("ldmatrix.sync.aligned.m8n8.x4.shared.b16 {%0,%1,%2,%3}, [%4];"
                 : "=r"(r0), "=r"(r1), "=r"(r2), "=r"(r3) : "r"(addr));
}
static __device__ __forceinline__ void ldsm2(u32& r0, u32& r1, u32 addr) {
    asm volatile("ldmatrix.sync.aligned.m8n8.x2.shared.b16 {%0,%1}, [%2];"
                 : "=r"(r0), "=r"(r1) : "r"(addr));
}
static __device__ __forceinline__ void mma16816(float* c, u32 a0, u32 a1, u32 a2, u32 a3,
                                                u32 b0, u32 b1) {
    asm volatile(
        "mma.sync.aligned.m16n8k16.row.col.f32.bf16.bf16.f32 "
        "{%0,%1,%2,%3}, {%4,%5,%6,%7}, {%8,%9}, {%0,%1,%2,%3};"
        : "+f"(c[0]), "+f"(c[1]), "+f"(c[2]), "+f"(c[3])
        : "r"(a0), "r"(a1), "r"(a2), "r"(a3), "r"(b0), "r"(b1));
}

// ---------------- softplus of factor tensors ----------------
__global__ void k_sp(const float* __restrict__ ff, const float* __restrict__ r1,
                     const float* __restrict__ r2) {
    int i = blockIdx.x * 256 + threadIdx.x;
    const int nF = NG * ZD * NF, nR = NG * ZD * NR;
    if (i < nF) g_spF[i] = softplusf(ff[i]);
    else if (i < nF + nR) g_spR1[i - nF] = softplusf(r1[i - nF]);
    else if (i < nF + 2 * nR) g_spR2[i - nF - nR] = softplusf(r2[i - nF - nR]);
}

// ---------------- per-group Gram products ----------------
__global__ void k_gram() {
    __shared__ float s1[ZD * NR], s2m[ZD * NR], sf[ZD * NF];
    int g = blockIdx.x, t = threadIdx.x;
    for (int i = t; i < ZD * NR; i += 256) {
        s1[i] = g_spR1[g * ZD * NR + i];
        s2m[i] = g_spR2[g * ZD * NR + i];
    }
    for (int i = t; i < ZD * NF; i += 256) sf[i] = g_spF[g * ZD * NF + i];
    __syncthreads();
    for (int q = t; q < ZD * ZD; q += 256) {
        int z = q >> 5, z2 = q & 31;
        float a = 0.f, b = 0.f, c = 0.f;
        #pragma unroll
        for (int r = 0; r < NR; r++) {
            a += s1[z * NR + r] * s1[z2 * NR + r];
            b += s2m[z * NR + r] * s2m[z2 * NR + r];
        }
        #pragma unroll
        for (int f = 0; f < NF; f++) c += sf[z * NF + f] * sf[z2 * NF + f];
        g_GG[g * ZD * ZD + q] = a * b * c;
    }
}

// ---------------- freq_loss + roi_loss ----------------
__global__ void k_varloss() {
    __shared__ float rf[256], rr[256];
    int t = threadIdx.x;
    float af = 0.f, ar = 0.f;
    for (int idx = t; idx < 4096; idx += 256) {
        float s = 0.f, ss = 0.f;
        if (idx < 2048) {
            #pragma unroll
            for (int g = 0; g < 16; g++) { float x = g_spF[g * 2048 + idx]; s += x; ss += x * x; }
            af += (ss - s * s * (1.f / 16.f)) * (1.f / 15.f);
        } else if (idx < 3072) {
            int j = idx - 2048;
            #pragma unroll
            for (int g = 0; g < 16; g++) { float x = g_spR1[g * 1024 + j]; s += x; ss += x * x; }
            ar += (ss - s * s * (1.f / 16.f)) * (1.f / 15.f);
        } else {
            int j = idx - 3072;
            #pragma unroll
            for (int g = 0; g < 16; g++) { float x = g_spR2[g * 1024 + j]; s += x; ss += x * x; }
            ar += (ss - s * s * (1.f / 16.f)) * (1.f / 15.f);
        }
    }
    rf[t] = af; rr[t] = ar;
    __syncthreads();
    for (int o = 128; o > 0; o >>= 1) {
        if (t < o) { rf[t] += rf[t + o]; rr[t] += rr[t + o]; }
        __syncthreads();
    }
    if (t == 0) g_varloss = rf[0] * (1.f / 64.f) + rr[0] * (1.f / 32.f);
}

// ---------------- deterministic counting sort by group (ballot-based) ----------------
__global__ void k_sort(const int* __restrict__ groups) {
    __shared__ int warpCnt[32][16];
    __shared__ int warpOff[32][16];
    __shared__ int goff[16], gcnt[16];
    int t = threadIdx.x, w = t >> 5, lane = t & 31;
    int g = groups[t];
    u32 mOwn = 0;
    #pragma unroll
    for (int gi = 0; gi < 16; gi++) {
        u32 m = __ballot_sync(0xffffffffu, g == gi);
        if (g == gi) mOwn = m;
        if (lane == gi) warpCnt[w][gi] = __popc(m);
    }
    __syncthreads();
    if (t < 16) {
        int s = 0;
        for (int w2 = 0; w2 < 32; w2++) { warpOff[w2][t] = s; s += warpCnt[w2][t]; }
        gcnt[t] = s;
    }
    __syncthreads();
    if (t == 0) {
        int s = 0;
        for (int i = 0; i < 16; i++) { goff[i] = s; s += gcnt[i]; }
    }
    __syncthreads();
    int rank = __popc(mOwn & ((1u << lane) - 1u));
    g_sIdx[goff[g] + warpOff[w][g] + rank] = t;
    if (t < 16) { g_gcnt[t] = gcnt[t]; g_goff[t] = goff[t]; }
}

// ---------------- transpose+convert W1|W2 -> WcT bf16 [64 n][65536 k] ----------------
// tiles of 64 k x 32 n; 512 threads; coalesced 128B reads and writes
__global__ void k_wcT(const float* __restrict__ W1, const float* __restrict__ W2) {
    __shared__ float tile[64][33];
    int w = blockIdx.y;
    int k0 = blockIdx.x * 64;
    int tx = threadIdx.x & 31, ty = threadIdx.x >> 5;   // 32 x 16
    const float* W = w ? W2 : W1;
    #pragma unroll
    for (int i = 0; i < 4; i++)
        tile[ty + 16 * i][tx] = W[(size_t)(k0 + ty + 16 * i) * 32 + tx];
    __syncthreads();
    int n = threadIdx.x >> 4;                 // 0..31
    int jj = (threadIdx.x & 15) * 2;          // u32 index 0..31 step 2
    u32* dst = (u32*)(g_WcT + (size_t)(w * 32 + n) * NFEAT + k0);
    #pragma unroll
    for (int q = 0; q < 2; q++) {
        int k = (jj + q) * 2;
        dst[jj + q] = cvt2(tile[k][n], tile[k + 1][n]);
    }
}

// ---------------- fused tensor-core GEMM ----------------
// grid (48 mtiles, KCS kc). CTA: 64 gathered rows x 96 cols x 4096 K.
// cols 0..63 = WcT (encoder), 64..95 = on-the-fly WP (rec-loss core). Fuses s2.
// Register prefetch of next A/B global tiles overlaps LDG latency with mma.
__global__ void __launch_bounds__(256) g_mm(const float* __restrict__ feat) {
    __shared__ __nv_bfloat16 As[64][72];
    __shared__ __nv_bfloat16 Bs[96][72];
    __shared__ float sF[ZD * NF];
    __shared__ float sR1[ZD * NR];
    __shared__ float sR2[ZD * NR];
    __shared__ int sIdx[64];

    int mt = blockIdx.x, kc = blockIdx.y;
    int g = mt / 3, ti = mt % 3;
    int nb = g_gcnt[g];
    int m0 = ti * 64;
    if (m0 >= nb) return;
    int goff = g_goff[g];
    int vr = nb - m0; if (vr > 64) vr = 64;
    int t = threadIdx.x;

    for (int i = t; i < ZD * NF; i += 256) sF[i] = g_spF[g * ZD * NF + i];
    for (int i = t; i < ZD * NR; i += 256) {
        sR1[i] = g_spR1[g * ZD * NR + i];
        sR2[i] = g_spR2[g * ZD * NR + i];
    }
    if (t < 64) sIdx[t] = (t < vr) ? g_sIdx[goff + m0 + t] : 0;
    __syncthreads();

    int lane = t & 31, wid = t >> 5;
    int wm = wid & 1, wn = wid >> 1;
    float acc[2][3][4];
    #pragma unroll
    for (int mf = 0; mf < 2; mf++)
        #pragma unroll
        for (int nf = 0; nf < 3; nf++)
            #pragma unroll
            for (int q = 0; q < 4; q++) acc[mf][nf][q] = 0.f;

    int ar = t >> 2, aq = t & 3;
    bool aval = ar < vr;
    const float* arow = feat + (size_t)sIdx[ar] * NFEAT;
    float sq = 0.f;

    int bn = t >> 2, bc = (t & 3) * 2;
    const uint4* brow = (const uint4*)(g_WcT + (size_t)bn * NFEAT);

    u32 sA = (u32)__cvta_generic_to_shared(&As[0][0]);
    u32 sB = (u32)__cvta_generic_to_shared(&Bs[0][0]);
    int kbase0 = kc * (NFEAT / KCS);

    float4 cA[4];
    uint4 cB[2];
    if (aval) {
        const float4* src = (const float4*)(arow + kbase0 + aq * 16);
        #pragma unroll
        for (int i = 0; i < 4; i++) cA[i] = src[i];
    }
    {
        const uint4* src = brow + (kbase0 >> 3);
        cB[0] = src[bc]; cB[1] = src[bc + 1];
    }

    for (int kt = 0; kt < NFEAT / KCS / 64; kt++) {
        int kb = kbase0 + kt * 64;
        // --- stage A (fp32 -> bf16, fused s2) ---
        {
            uint4 o0 = {0, 0, 0, 0}, o1 = {0, 0, 0, 0};
            if (aval) {
                #pragma unroll
                for (int i = 0; i < 4; i++)
                    sq += cA[i].x * cA[i].x + cA[i].y * cA[i].y +
                          cA[i].z * cA[i].z + cA[i].w * cA[i].w;
                o0.x = cvt2(cA[0].x, cA[0].y); o0.y = cvt2(cA[0].z, cA[0].w);
                o0.z = cvt2(cA[1].x, cA[1].y); o0.w = cvt2(cA[1].z, cA[1].w);
                o1.x = cvt2(cA[2].x, cA[2].y); o1.y = cvt2(cA[2].z, cA[2].w);
                o1.z = cvt2(cA[3].x, cA[3].y); o1.w = cvt2(cA[3].z, cA[3].w);
            }
            *(uint4*)&As[ar][aq * 16] = o0;
            *(uint4*)&As[ar][aq * 16 + 8] = o1;
        }
        // --- stage B rows 0..63 ---
        {
            uint4* dst = (uint4*)&Bs[bn][0];
            dst[bc] = cB[0];
            dst[bc + 1] = cB[1];
        }
        // --- stage B rows 64..95: WP on the fly ---
        {
            int z = t >> 3, i0 = (t & 7) * 8;
            int f = kb >> 10, r0 = (kb >> 5) & 31;
            float c0 = sF[z * NF + f] * sR1[z * NR + r0 + (i0 >> 5)];
            int s0 = i0 & 31;
            u32* dst = (u32*)&Bs[64 + z][i0];
            #pragma unroll
            for (int j = 0; j < 4; j++)
                dst[j] = cvt2(c0 * sR2[z * NR + s0 + 2 * j],
                              c0 * sR2[z * NR + s0 + 2 * j + 1]);
        }
        __syncthreads();
        // --- prefetch next global tiles (overlaps with mma below) ---
        if (kt < NFEAT / KCS / 64 - 1) {
            int kbn = kb + 64;
            if (aval) {
                const float4* src = (const float4*)(arow + kbn + aq * 16);
                #pragma unroll
                for (int i = 0; i < 4; i++) cA[i] = src[i];
            }
            const uint4* src = brow + (kbn >> 3);
            cB[0] = src[bc]; cB[1] = src[bc + 1];
        }
        // --- mma ---
        #pragma unroll
        for (int ks = 0; ks < 4; ks++) {
            int kbs = ks * 16;
            u32 b0[3], b1[3];
            #pragma unroll
            for (int nf = 0; nf < 3; nf++) {
                int n = wn * 24 + nf * 8 + (lane & 7);
                u32 addr = sB + (u32)(n * 72 + kbs + ((lane >> 3) & 1) * 8) * 2;
                ldsm2(b0[nf], b1[nf], addr);
            }
            #pragma unroll
            for (int mf = 0; mf < 2; mf++) {
                int row = wm * 32 + mf * 16 + (lane & 15);
                u32 addr = sA + (u32)(row * 72 + kbs + (lane >> 4) * 8) * 2;
                u32 a0, a1, a2, a3;
                ldsm4(a0, a1, a2, a3, addr);
                #pragma unroll
                for (int nf = 0; nf < 3; nf++)
                    mma16816(acc[mf][nf], a0, a1, a2, a3, b0[nf], b1[nf]);
            }
        }
        __syncthreads();
    }
    // s2 partial (4 threads per row)
    sq += __shfl_down_sync(0xffffffffu, sq, 2, 4);
    sq += __shfl_down_sync(0xffffffffu, sq, 1, 4);
    if (aq == 0 && aval) g_s2part[kc * BATCH + goff + m0 + ar] = sq;
    // epilogue: scatter fp32 partials
    #pragma unroll
    for (int mf = 0; mf < 2; mf++) {
        #pragma unroll
        for (int half = 0; half < 2; half++) {
            int r = wm * 32 + mf * 16 + (lane >> 2) + half * 8;
            if (r < vr) {
                int p = goff + m0 + r;
                float* dst = g_zpart + ((size_t)kc * BATCH + p) * 96;
                #pragma unroll
                for (int nf = 0; nf < 3; nf++) {
                    int ncol = wn * 24 + nf * 8 + (lane & 3) * 2;
                    float2 v = half ? make_float2(acc[mf][nf][2], acc[mf][nf][3])
                                    : make_float2(acc[mf][nf][0], acc[mf][nf][1]);
                    *(float2*)(dst + ncol) = v;
                }
            }
        }
    }
}

// ---------------- reduce split-K partials; scatter sorted->original ----------------
__global__ void k_red() {
    int i = blockIdx.x * 256 + threadIdx.x;
    if (i < BATCH * 96) {
        int p = i / 96, n = i - p * 96;
        float s = 0.f;
        for (int kc = 0; kc < KCS; kc++) s += g_zpart[((size_t)kc * BATCH + p) * 96 + n];
        int b = g_sIdx[p];
        if (n < 64) g_zraw[b * 64 + n] = s;
        else g_PF[b * 32 + n - 64] = s;
    } else if (i < BATCH * 96 + BATCH) {
        int p = i - BATCH * 96;
        float s = 0.f;
        for (int kc = 0; kc < KCS; kc++) s += g_s2part[kc * BATCH + p];
        g_s2[g_sIdx[p]] = s;
    }
}

// ---------------- VAE head ----------------
__global__ void k_vae(const float* __restrict__ W1, const float* __restrict__ W2,
                      const float* __restrict__ b1, const float* __restrict__ b2,
                      const float* __restrict__ ge, const int* __restrict__ groups,
                      const float* __restrict__ noise, const float* __restrict__ linW,
                      const float* __restrict__ linb) {
    int t = threadIdx.x, b = blockIdx.x * 8 + (t >> 5), z = t & 31;
    int g = groups[b];
    float e0 = ge[g * 2], e1 = ge[g * 2 + 1];
    float mu = g_zraw[b * 64 + z] + b1[z] + e0 * W1[65536 * 32 + z] + e1 * W1[65537 * 32 + z];
    float ls = g_zraw[b * 64 + 32 + z] + b2[z] + e0 * W2[65536 * 32 + z] + e1 * W2[65537 * 32 + z];
    float sig = 1e-6f + expf(ls);
    float kt = -logf(sig) + 0.5f * (sig * sig + mu * mu - 1.f);
    #pragma unroll
    for (int o = 16; o > 0; o >>= 1) kt += __shfl_xor_sync(0xffffffffu, kt, o);
    if (z == 0) g_kld[b] = kt;
    float zs = mu + sig * noise[b * 32 + z];
    float acc = linb[z];
    #pragma unroll
    for (int k = 0; k < 32; k++)
        acc += __shfl_sync(0xffffffffu, zs, k) * linW[k * 32 + z];
    g_zs2[b * 32 + z] = acc;
    g_w[b * 32 + z] = softplusf(acc);
}

// ---------------- per-sample assembly ----------------
__global__ void k_asm(const float* __restrict__ weights, const int* __restrict__ labels,
                      const int* __restrict__ groups, const float* __restrict__ lbias) {
    int t = threadIdx.x, b = blockIdx.x * 8 + (t >> 5), z = t & 31;
    int g = groups[b];
    float w = g_w[b * 32 + z];
    float red = -2.f * w * g_PF[b * 32 + z];
    const float* GG = g_GG + g * 1024 + z * 32;
    float vs = 0.f;
    #pragma unroll
    for (int k = 0; k < 32; k++) vs += GG[k] * __shfl_sync(0xffffffffu, w, k);
    red += w * vs;
    #pragma unroll
    for (int o = 16; o > 0; o >>= 1) red += __shfl_xor_sync(0xffffffffu, red, o);
    if (z == 0) {
        float rec = (g_s2[b] + red) * (1.f / 65536.f);
        float l0 = g_zs2[b * 32 + 0] + lbias[0];
        float l1 = g_zs2[b * 32 + 1] + lbias[1];
        float l2 = g_zs2[b * 32 + 2] + lbias[2];
        float l3 = 1.f + lbias[3];
        float m = fmaxf(fmaxf(l0, l1), fmaxf(l2, l3));
        float lse = m + logf(expf(l0 - m) + expf(l1 - m) + expf(l2 - m) + expf(l3 - m));
        int lab = labels[b];
        float ll = (lab == 0 ? l0 : lab == 1 ? l1 : lab == 2 ? l2 : l3) - lse;
        g_perb[b] = rec - weights[b] * ll + g_kld[b];
    }
}

__global__ void k_final(float* out) {
    __shared__ float red[256];
    int t = threadIdx.x;
    red[t] = g_perb[t] + g_perb[t + 256] + g_perb[t + 512] + g_perb[t + 768];
    __syncthreads();
    for (int o = 128; o > 0; o >>= 1) {
        if (t < o) red[t] += red[t + o];
        __syncthreads();
    }
    if (t == 0) out[0] = red[0] * (1.f / 1024.f) + g_varloss;
}

extern "C" void kernel_launch(void* const* d_in, const int* in_sizes, int n_in,
                              void* d_out, int out_size) {
    const float* feat    = (const float*)d_in[0];
    const int*   labels  = (const int*)d_in[1];
    const int*   groups  = (const int*)d_in[2];
    const float* weights = (const float*)d_in[3];
    const float* noise   = (const float*)d_in[4];
    const float* ge      = (const float*)d_in[5];
    const float* W1      = (const float*)d_in[6];
    const float* b1      = (const float*)d_in[7];
    const float* W2      = (const float*)d_in[8];
    const float* b2      = (const float*)d_in[9];
    const float* ff      = (const float*)d_in[10];
    const float* r1      = (const float*)d_in[11];
    const float* r2      = (const float*)d_in[12];
    const float* linW    = (const float*)d_in[13];
    const float* linb    = (const float*)d_in[14];
    const float* lbias   = (const float*)d_in[15];
    float* out = (float*)d_out;

    k_sp<<<256, 256>>>(ff, r1, r2);
    k_gram<<<16, 256>>>();
    k_varloss<<<1, 256>>>();
    k_sort<<<1, 1024>>>(groups);
    k_wcT<<<dim3(1024, 2), 512>>>(W1, W2);
    g_mm<<<dim3(48, KCS), 256>>>(feat);
    k_red<<<388, 256>>>();
    k_vae<<<128, 256>>>(W1, W2, b1, b2, ge, groups, noise, linW, linb);
    k_asm<<<128, 256>>>(weights, labels, groups, lbias);
    k_final<<<1, 256>>>(out);
}

// round 8
// speedup vs baseline: 1.9694x; 1.0296x over previous
#include <cuda_runtime.h>
#include <cuda_bf16.h>
#include <math.h>

#define BATCH 1024
#define NFEAT 65536
#define ZD 32
#define NG 16
#define NF 64
#define NR 32
#define KCS 16
#define KPC (NFEAT / KCS)     // 4096 K per CTA
#define NSTG (KPC / 64)       // 64 stages of BK=64

typedef unsigned int u32;

__device__ float g_zpart[KCS * BATCH * 96];
__device__ float g_s2part[KCS * BATCH];
__device__ float g_zraw[BATCH * 64];
__device__ float g_PF[BATCH * ZD];
__device__ float g_s2[BATCH];
__device__ float g_spF[NG * ZD * NF];
__device__ float g_spR1[NG * ZD * NR];
__device__ float g_spR2[NG * ZD * NR];
__device__ float g_GG[NG * ZD * ZD];
__device__ float g_w[BATCH * ZD];
__device__ float g_zs2[BATCH * ZD];
__device__ float g_kld[BATCH];
__device__ float g_perb[BATCH];
__device__ float g_varloss;
__device__ __nv_bfloat16 g_WcT[64 * NFEAT];   // [n][k] bf16 W1|W2 transposed
__device__ int g_sIdx[BATCH];
__device__ int g_gcnt[NG];
__device__ int g_goff[NG];

// dynamic smem layout (bytes)
#define SMO_A    0u           // 2 slots x 64 rows x 72 bf16  (9216 B/slot)
#define SMO_B    18432u       // 2 slots x 96 rows x 72 bf16  (13824 B/slot)
#define SMO_F    46080u       // 2048 floats
#define SMO_R1   54272u       // 1024 floats
#define SMO_R2   58368u       // 1024 floats
#define SMO_IDX  62464u       // 64 ints
#define SM_TOT   62720u

static __device__ __forceinline__ float softplusf(float x) {
    return fmaxf(x, 0.f) + log1pf(expf(-fabsf(x)));
}
static __device__ __forceinline__ u32 cvt2(float a, float b) {
    __nv_bfloat162 h = __floats2bfloat162_rn(a, b);
    return *reinterpret_cast<u32*>(&h);
}
static __device__ __forceinline__ void cpa16(u32 dst, const void* src) {
    asm volatile("cp.async.cg.shared.global [%0], [%1], 16;" :: "r"(dst), "l"(src) : "memory");
}
static __device__ __forceinline__ void sts128(u32 addr, u32 x, u32 y, u32 z, u32 w) {
    asm volatile("st.shared.v4.b32 [%0], {%1,%2,%3,%4};"
                 :: "r"(addr), "r"(x), "r"(y), "r"(z), "r"(w) : "memory");
}
static __device__ __forceinline__ void ldsm4(u32& r0, u32& r1, u32& r2, u32& r3, u32 addr) {
    asm volatile("ldmatrix.sync.aligned.m8n8.x4.shared.b16 {%0,%1,%2,%3}, [%4];"
                 : "=r"(r0), "=r"(r1), "=r"(r2), "=r"(r3) : "r"(addr));
}
static __device__ __forceinline__ void ldsm2(u32& r0, u32& r1, u32 addr) {
    asm volatile("ldmatrix.sync.aligned.m8n8.x2.shared.b16 {%0,%1}, [%2];"
                 : "=r"(r0), "=r"(r1) : "r"(addr));
}
static __device__ __forceinline__ void mma16816(float* c, u32 a0, u32 a1, u32 a2, u32 a3,
                                                u32 b0, u32 b1) {
    asm volatile(
        "mma.sync.aligned.m16n8k16.row.col.f32.bf16.bf16.f32 "
        "{%0,%1,%2,%3}, {%4,%5,%6,%7}, {%8,%9}, {%0,%1,%2,%3};"
        : "+f"(c[0]), "+f"(c[1]), "+f"(c[2]), "+f"(c[3])
        : "r"(a0), "r"(a1), "r"(a2), "r"(a3), "r"(b0), "r"(b1));
}

// ---------------- softplus of factor tensors ----------------
__global__ void k_sp(const float* __restrict__ ff, const float* __restrict__ r1,
                     const float* __restrict__ r2) {
    int i = blockIdx.x * 256 + threadIdx.x;
    const int nF = NG * ZD * NF, nR = NG * ZD * NR;
    if (i < nF) g_spF[i] = softplusf(ff[i]);
    else if (i < nF + nR) g_spR1[i - nF] = softplusf(r1[i - nF]);
    else if (i < nF + 2 * nR) g_spR2[i - nF - nR] = softplusf(r2[i - nF - nR]);
}

// ---------------- per-group Gram products ----------------
__global__ void k_gram() {
    __shared__ float s1[ZD * NR], s2m[ZD * NR], sf[ZD * NF];
    int g = blockIdx.x, t = threadIdx.x;
    for (int i = t; i < ZD * NR; i += 256) {
        s1[i] = g_spR1[g * ZD * NR + i];
        s2m[i] = g_spR2[g * ZD * NR + i];
    }
    for (int i = t; i < ZD * NF; i += 256) sf[i] = g_spF[g * ZD * NF + i];
    __syncthreads();
    for (int q = t; q < ZD * ZD; q += 256) {
        int z = q >> 5, z2 = q & 31;
        float a = 0.f, b = 0.f, c = 0.f;
        #pragma unroll
        for (int r = 0; r < NR; r++) {
            a += s1[z * NR + r] * s1[z2 * NR + r];
            b += s2m[z * NR + r] * s2m[z2 * NR + r];
        }
        #pragma unroll
        for (int f = 0; f < NF; f++) c += sf[z * NF + f] * sf[z2 * NF + f];
        g_GG[g * ZD * ZD + q] = a * b * c;
    }
}

// ---------------- freq_loss + roi_loss ----------------
__global__ void k_varloss() {
    __shared__ float rf[256], rr[256];
    int t = threadIdx.x;
    float af = 0.f, ar = 0.f;
    for (int idx = t; idx < 4096; idx += 256) {
        float s = 0.f, ss = 0.f;
        if (idx < 2048) {
            #pragma unroll
            for (int g = 0; g < 16; g++) { float x = g_spF[g * 2048 + idx]; s += x; ss += x * x; }
            af += (ss - s * s * (1.f / 16.f)) * (1.f / 15.f);
        } else if (idx < 3072) {
            int j = idx - 2048;
            #pragma unroll
            for (int g = 0; g < 16; g++) { float x = g_spR1[g * 1024 + j]; s += x; ss += x * x; }
            ar += (ss - s * s * (1.f / 16.f)) * (1.f / 15.f);
        } else {
            int j = idx - 3072;
            #pragma unroll
            for (int g = 0; g < 16; g++) { float x = g_spR2[g * 1024 + j]; s += x; ss += x * x; }
            ar += (ss - s * s * (1.f / 16.f)) * (1.f / 15.f);
        }
    }
    rf[t] = af; rr[t] = ar;
    __syncthreads();
    for (int o = 128; o > 0; o >>= 1) {
        if (t < o) { rf[t] += rf[t + o]; rr[t] += rr[t + o]; }
        __syncthreads();
    }
    if (t == 0) g_varloss = rf[0] * (1.f / 64.f) + rr[0] * (1.f / 32.f);
}

// ---------------- deterministic counting sort by group (ballot-based) ----------------
__global__ void k_sort(const int* __restrict__ groups) {
    __shared__ int warpCnt[32][16];
    __shared__ int warpOff[32][16];
    __shared__ int goff[16], gcnt[16];
    int t = threadIdx.x, w = t >> 5, lane = t & 31;
    int g = groups[t];
    u32 mOwn = 0;
    #pragma unroll
    for (int gi = 0; gi < 16; gi++) {
        u32 m = __ballot_sync(0xffffffffu, g == gi);
        if (g == gi) mOwn = m;
        if (lane == gi) warpCnt[w][gi] = __popc(m);
    }
    __syncthreads();
    if (t < 16) {
        int s = 0;
        for (int w2 = 0; w2 < 32; w2++) { warpOff[w2][t] = s; s += warpCnt[w2][t]; }
        gcnt[t] = s;
    }
    __syncthreads();
    if (t == 0) {
        int s = 0;
        for (int i = 0; i < 16; i++) { goff[i] = s; s += gcnt[i]; }
    }
    __syncthreads();
    int rank = __popc(mOwn & ((1u << lane) - 1u));
    g_sIdx[goff[g] + warpOff[w][g] + rank] = t;
    if (t < 16) { g_gcnt[t] = gcnt[t]; g_goff[t] = goff[t]; }
}

// ---------------- transpose+convert W1|W2 -> WcT bf16 [64 n][65536 k] ----------------
__global__ void k_wcT(const float* __restrict__ W1, const float* __restrict__ W2) {
    __shared__ float tile[64][33];
    int w = blockIdx.y;
    int k0 = blockIdx.x * 64;
    int tx = threadIdx.x & 31, ty = threadIdx.x >> 5;
    const float* W = w ? W2 : W1;
    #pragma unroll
    for (int i = 0; i < 4; i++)
        tile[ty + 16 * i][tx] = W[(size_t)(k0 + ty + 16 * i) * 32 + tx];
    __syncthreads();
    int n = threadIdx.x >> 4;
    int jj = (threadIdx.x & 15) * 2;
    u32* dst = (u32*)(g_WcT + (size_t)(w * 32 + n) * NFEAT + k0);
    #pragma unroll
    for (int q = 0; q < 2; q++) {
        int k = (jj + q) * 2;
        dst[jj + q] = cvt2(tile[k][n], tile[k + 1][n]);
    }
}

// ---------------- fused tensor-core GEMM (mma.sync, double-buffered, cp.async B) ----
// grid (48 mtiles, KCS kc). CTA: 64 gathered rows x 96 cols x 4096 K.
// cols 0..63 encoder (WcT), 64..95 on-the-fly WP. Fuses exact s2.
__global__ void __launch_bounds__(256) g_mm(const float* __restrict__ feat) {
    extern __shared__ char smc[];
    u32 sbase = (u32)__cvta_generic_to_shared(smc);
    float* sF = (float*)(smc + SMO_F);
    float* sR1 = (float*)(smc + SMO_R1);
    float* sR2 = (float*)(smc + SMO_R2);
    int* sIdx = (int*)(smc + SMO_IDX);

    int mt = blockIdx.x, kc = blockIdx.y;
    int g = mt / 3, ti = mt % 3;
    int nb = g_gcnt[g];
    int m0 = ti * 64;
    if (m0 >= nb) return;
    int p0 = g_goff[g] + m0;
    int vr = nb - m0; if (vr > 64) vr = 64;
    int t = threadIdx.x;

    for (int i = t; i < ZD * NF; i += 256) sF[i] = g_spF[g * ZD * NF + i];
    for (int i = t; i < ZD * NR; i += 256) {
        sR1[i] = g_spR1[g * ZD * NR + i];
        sR2[i] = g_spR2[g * ZD * NR + i];
    }
    if (t < 64) sIdx[t] = g_sIdx[(t < vr) ? (p0 + t) : p0];
    __syncthreads();

    int lane = t & 31, wid = t >> 5;
    int wm = wid & 1, wn = wid >> 1;
    float acc[2][3][4];
    #pragma unroll
    for (int mf = 0; mf < 2; mf++)
        #pragma unroll
        for (int nf = 0; nf < 3; nf++)
            #pragma unroll
            for (int q = 0; q < 4; q++) acc[mf][nf][q] = 0.f;

    int ar = t >> 2, aq = t & 3;
    bool aval = ar < vr;
    const float* arow = feat + (size_t)sIdx[ar] * NFEAT + aq * 16;
    int wz = t >> 3, wi0 = (t & 7) * 8;          // WP mapping
    int kb0 = kc * KPC;
    float sq = 0.f;

    // B cp.async stage: 64 rows x 128B from WcT; 4 threads/row x 32B each
    int brow = t >> 2, bch = (t & 3) * 2;
    const char* bsrc = (const char*)(g_WcT + (size_t)brow * NFEAT) + bch * 16;
    u32 bdstBase = sbase + SMO_B + (u32)brow * 144 + (u32)bch * 16;

    #define STAGE_B(s, kb)                                                        \
        do {                                                                      \
            u32 _d = bdstBase + ((u32)(s) & 1u) * 13824u;                         \
            const char* _s = bsrc + (size_t)(kb) * 2;                             \
            cpa16(_d, _s); cpa16(_d + 16, _s + 16);                               \
            asm volatile("cp.async.commit_group;");                               \
        } while (0)

    #define STAGE_AWP(s, kb, rg)                                                  \
        do {                                                                      \
            u32 _ab = sbase + SMO_A + ((u32)(s) & 1u) * 9216u + (u32)ar * 144 + (u32)aq * 32; \
            if (aval) {                                                           \
                sq += rg[0].x * rg[0].x + rg[0].y * rg[0].y + rg[0].z * rg[0].z + rg[0].w * rg[0].w; \
                sq += rg[1].x * rg[1].x + rg[1].y * rg[1].y + rg[1].z * rg[1].z + rg[1].w * rg[1].w; \
                sq += rg[2].x * rg[2].x + rg[2].y * rg[2].y + rg[2].z * rg[2].z + rg[2].w * rg[2].w; \
                sq += rg[3].x * rg[3].x + rg[3].y * rg[3].y + rg[3].z * rg[3].z + rg[3].w * rg[3].w; \
            }                                                                     \
            sts128(_ab, cvt2(rg[0].x, rg[0].y), cvt2(rg[0].z, rg[0].w),           \
                        cvt2(rg[1].x, rg[1].y), cvt2(rg[1].z, rg[1].w));          \
            sts128(_ab + 16, cvt2(rg[2].x, rg[2].y), cvt2(rg[2].z, rg[2].w),      \
                             cvt2(rg[3].x, rg[3].y), cvt2(rg[3].z, rg[3].w));     \
            int _f = (kb) >> 10, _r0 = ((kb) >> 5) & 31;                          \
            float _c0 = sF[wz * NF + _f] * sR1[wz * NR + _r0 + (wi0 >> 5)];       \
            int _s0 = wi0 & 31;                                                   \
            sts128(sbase + SMO_B + ((u32)(s) & 1u) * 13824u + (u32)(64 + wz) * 144 + (u32)wi0 * 2, \
                   cvt2(_c0 * sR2[wz * NR + _s0 + 0], _c0 * sR2[wz * NR + _s0 + 1]), \
                   cvt2(_c0 * sR2[wz * NR + _s0 + 2], _c0 * sR2[wz * NR + _s0 + 3]), \
                   cvt2(_c0 * sR2[wz * NR + _s0 + 4], _c0 * sR2[wz * NR + _s0 + 5]), \
                   cvt2(_c0 * sR2[wz * NR + _s0 + 6], _c0 * sR2[wz * NR + _s0 + 7])); \
        } while (0)

    float4 rNext[4], rFar[4];
    // prologue: B(0), B(1) in flight; A(0) staged; rNext = A(1)
    STAGE_B(0, kb0);
    STAGE_B(1, kb0 + 64);
    {
        float4 rNow[4] = {};
        if (aval) {
            const float4* s4 = (const float4*)(arow + kb0);
            #pragma unroll
            for (int i = 0; i < 4; i++) rNow[i] = s4[i];
            const float4* s5 = (const float4*)(arow + kb0 + 64);
            #pragma unroll
            for (int i = 0; i < 4; i++) rNext[i] = s5[i];
        }
        STAGE_AWP(0, kb0, rNow);
    }

    for (int kt = 0; kt < NSTG; kt++) {
        asm volatile("cp.async.wait_group 1;");
        __syncthreads();
        // LDG prefetch A(kt+2)
        if (aval && kt + 2 < NSTG) {
            const float4* s4 = (const float4*)(arow + kb0 + (kt + 2) * 64);
            #pragma unroll
            for (int i = 0; i < 4; i++) rFar[i] = s4[i];
        }
        // mma on slot kt
        {
            u32 aBase = sbase + SMO_A + ((u32)kt & 1u) * 9216u;
            u32 bBase = sbase + SMO_B + ((u32)kt & 1u) * 13824u;
            #pragma unroll
            for (int ks = 0; ks < 4; ks++) {
                int kbs = ks * 16;
                u32 b0[3], b1[3];
                #pragma unroll
                for (int nf = 0; nf < 3; nf++) {
                    int n = wn * 24 + nf * 8 + (lane & 7);
                    ldsm2(b0[nf], b1[nf], bBase + (u32)(n * 72 + kbs + ((lane >> 3) & 1) * 8) * 2);
                }
                #pragma unroll
                for (int mf = 0; mf < 2; mf++) {
                    int row = wm * 32 + mf * 16 + (lane & 15);
                    u32 a0, a1, a2, a3;
                    ldsm4(a0, a1, a2, a3, aBase + (u32)(row * 72 + kbs + (lane >> 4) * 8) * 2);
                    #pragma unroll
                    for (int nf = 0; nf < 3; nf++)
                        mma16816(acc[mf][nf], a0, a1, a2, a3, b0[nf], b1[nf]);
                }
            }
        }
        __syncthreads();   // all warps done reading slot kt before it is overwritten
        // stage kt+1 (A from rNext, WP) into slot kt+1; cp.async B(kt+2) into slot kt
        if (kt + 1 < NSTG) {
            STAGE_AWP(kt + 1, kb0 + (kt + 1) * 64, rNext);
            if (kt + 2 < NSTG) {
                STAGE_B(kt + 2, kb0 + (kt + 2) * 64);
            } else {
                asm volatile("cp.async.commit_group;");
            }
            #pragma unroll
            for (int i = 0; i < 4; i++) rNext[i] = rFar[i];
        } else {
            asm volatile("cp.async.commit_group;");
        }
    }

    // s2 partials (4 threads per row)
    sq += __shfl_down_sync(0xffffffffu, sq, 2, 4);
    sq += __shfl_down_sync(0xffffffffu, sq, 1, 4);
    if (aq == 0 && aval) g_s2part[kc * BATCH + p0 + ar] = sq;

    // epilogue: scatter fp32 partials
    #pragma unroll
    for (int mf = 0; mf < 2; mf++) {
        #pragma unroll
        for (int half = 0; half < 2; half++) {
            int r = wm * 32 + mf * 16 + (lane >> 2) + half * 8;
            if (r < vr) {
                int p = p0 + r;
                float* dst = g_zpart + ((size_t)kc * BATCH + p) * 96;
                #pragma unroll
                for (int nf = 0; nf < 3; nf++) {
                    int ncol = wn * 24 + nf * 8 + (lane & 3) * 2;
                    float2 v = half ? make_float2(acc[mf][nf][2], acc[mf][nf][3])
                                    : make_float2(acc[mf][nf][0], acc[mf][nf][1]);
                    *(float2*)(dst + ncol) = v;
                }
            }
        }
    }
    #undef STAGE_B
    #undef STAGE_AWP
}

// ---------------- reduce split-K partials; scatter sorted->original ----------------
__global__ void k_red() {
    int i = blockIdx.x * 256 + threadIdx.x;
    if (i < BATCH * 96) {
        int p = i / 96, n = i - p * 96;
        float s = 0.f;
        for (int kc = 0; kc < KCS; kc++) s += g_zpart[((size_t)kc * BATCH + p) * 96 + n];
        int b = g_sIdx[p];
        if (n < 64) g_zraw[b * 64 + n] = s;
        else g_PF[b * 32 + n - 64] = s;
    } else if (i < BATCH * 96 + BATCH) {
        int p = i - BATCH * 96;
        float s = 0.f;
        for (int kc = 0; kc < KCS; kc++) s += g_s2part[kc * BATCH + p];
        g_s2[g_sIdx[p]] = s;
    }
}

// ---------------- VAE head ----------------
__global__ void k_vae(const float* __restrict__ W1, const float* __restrict__ W2,
                      const float* __restrict__ b1, const float* __restrict__ b2,
                      const float* __restrict__ ge, const int* __restrict__ groups,
                      const float* __restrict__ noise, const float* __restrict__ linW,
                      const float* __restrict__ linb) {
    int t = threadIdx.x, b = blockIdx.x * 8 + (t >> 5), z = t & 31;
    int g = groups[b];
    float e0 = ge[g * 2], e1 = ge[g * 2 + 1];
    float mu = g_zraw[b * 64 + z] + b1[z] + e0 * W1[65536 * 32 + z] + e1 * W1[65537 * 32 + z];
    float ls = g_zraw[b * 64 + 32 + z] + b2[z] + e0 * W2[65536 * 32 + z] + e1 * W2[65537 * 32 + z];
    float sig = 1e-6f + expf(ls);
    float kt = -logf(sig) + 0.5f * (sig * sig + mu * mu - 1.f);
    #pragma unroll
    for (int o = 16; o > 0; o >>= 1) kt += __shfl_xor_sync(0xffffffffu, kt, o);
    if (z == 0) g_kld[b] = kt;
    float zs = mu + sig * noise[b * 32 + z];
    float acc = linb[z];
    #pragma unroll
    for (int k = 0; k < 32; k++)
        acc += __shfl_sync(0xffffffffu, zs, k) * linW[k * 32 + z];
    g_zs2[b * 32 + z] = acc;
    g_w[b * 32 + z] = softplusf(acc);
}

// ---------------- per-sample assembly ----------------
__global__ void k_asm(const float* __restrict__ weights, const int* __restrict__ labels,
                      const int* __restrict__ groups, const float* __restrict__ lbias) {
    int t = threadIdx.x, b = blockIdx.x * 8 + (t >> 5), z = t & 31;
    int g = groups[b];
    float w = g_w[b * 32 + z];
    float red = -2.f * w * g_PF[b * 32 + z];
    const float* GG = g_GG + g * 1024 + z * 32;
    float vs = 0.f;
    #pragma unroll
    for (int k = 0; k < 32; k++) vs += GG[k] * __shfl_sync(0xffffffffu, w, k);
    red += w * vs;
    #pragma unroll
    for (int o = 16; o > 0; o >>= 1) red += __shfl_xor_sync(0xffffffffu, red, o);
    if (z == 0) {
        float rec = (g_s2[b] + red) * (1.f / 65536.f);
        float l0 = g_zs2[b * 32 + 0] + lbias[0];
        float l1 = g_zs2[b * 32 + 1] + lbias[1];
        float l2 = g_zs2[b * 32 + 2] + lbias[2];
        float l3 = 1.f + lbias[3];
        float m = fmaxf(fmaxf(l0, l1), fmaxf(l2, l3));
        float lse = m + logf(expf(l0 - m) + expf(l1 - m) + expf(l2 - m) + expf(l3 - m));
        int lab = labels[b];
        float ll = (lab == 0 ? l0 : lab == 1 ? l1 : lab == 2 ? l2 : l3) - lse;
        g_perb[b] = rec - weights[b] * ll + g_kld[b];
    }
}

__global__ void k_final(float* out) {
    __shared__ float red[256];
    int t = threadIdx.x;
    red[t] = g_perb[t] + g_perb[t + 256] + g_perb[t + 512] + g_perb[t + 768];
    __syncthreads();
    for (int o = 128; o > 0; o >>= 1) {
        if (t < o) red[t] += red[t + o];
        __syncthreads();
    }
    if (t == 0) out[0] = red[0] * (1.f / 1024.f) + g_varloss;
}

extern "C" void kernel_launch(void* const* d_in, const int* in_sizes, int n_in,
                              void* d_out, int out_size) {
    const float* feat    = (const float*)d_in[0];
    const int*   labels  = (const int*)d_in[1];
    const int*   groups  = (const int*)d_in[2];
    const float* weights = (const float*)d_in[3];
    const float* noise   = (const float*)d_in[4];
    const float* ge      = (const float*)d_in[5];
    const float* W1      = (const float*)d_in[6];
    const float* b1      = (const float*)d_in[7];
    const float* W2      = (const float*)d_in[8];
    const float* b2      = (const float*)d_in[9];
    const float* ff      = (const float*)d_in[10];
    const float* r1      = (const float*)d_in[11];
    const float* r2      = (const float*)d_in[12];
    const float* linW    = (const float*)d_in[13];
    const float* linb    = (const float*)d_in[14];
    const float* lbias   = (const float*)d_in[15];
    float* out = (float*)d_out;

    cudaFuncSetAttribute(g_mm, cudaFuncAttributeMaxDynamicSharedMemorySize, SM_TOT);

    k_sp<<<256, 256>>>(ff, r1, r2);
    k_gram<<<16, 256>>>();
    k_varloss<<<1, 256>>>();
    k_sort<<<1, 1024>>>(groups);
    k_wcT<<<dim3(1024, 2), 512>>>(W1, W2);
    g_mm<<<dim3(48, KCS), 256, SM_TOT>>>(feat);
    k_red<<<388, 256>>>();
    k_vae<<<128, 256>>>(W1, W2, b1, b2, ge, groups, noise, linW, linb);
    k_asm<<<128, 256>>>(weights, labels, groups, lbias);
    k_final<<<1, 256>>>(out);
}